// round 12
// baseline (speedup 1.0000x reference)
#include <cuda_runtime.h>
#include <math.h>
#include <float.h>

#define BB 8
#define CC 64
#define NN 65536
#define HEADS 8
#define C3 192
#define TOT (BB*CC*NN)
#define SBLK 2048                 // sort scatter block size (items)
#define NBLK (NN/SBLK)            // 32 sub-blocks per segment
typedef unsigned long long ull;

// ------------------- static scratch -------------------
__device__ __align__(256) float g_x[TOT];                 // sorted x; later v_s floats
__device__ __align__(256) float g_qkv[BB*C3*NN];          // qkv; later id u16 array
__device__ __align__(256) float g_dw[BB*128*NN];          // interleaved (q,k) float2
__device__ __align__(256) ull g_keys0[TOT];               // K0 (u32) + P0 (u16)
__device__ __align__(256) ull g_keys1[TOT];               // K1 + P1
__device__ __align__(256) float g_out[TOT];
__device__ unsigned g_cntA[512*NBLK*256];
__device__ unsigned g_cntB[512*NBLK*256];
__device__ unsigned g_cntC[512*NBLK*256];
__device__ unsigned char g_idxh[BB*32*NN];
__device__ unsigned char g_idxw[BB*32*NN];
__device__ float g_nq[BB*CC], g_nk[BB*CC];
__device__ float g_attnraw[BB*HEADS*64];
__device__ float g_attn[BB*HEADS*64];
__device__ float g_chsum[BB*CC];
__device__ unsigned g_chmaxu[BB*CC];
__device__ float g_ca[BB*CC];
__device__ float g_sp[BB*4*NN];
__device__ float g_sa[BB*NN];

// ------------------- helpers -------------------
__device__ __forceinline__ unsigned fkey(float f) {
    unsigned u = __float_as_uint(f);
    return (u & 0x80000000u) ? ~u : (u | 0x80000000u);
}
__device__ __forceinline__ float fdec(unsigned k) {
    return __uint_as_float((k & 0x80000000u) ? (k ^ 0x80000000u) : ~k);
}
__device__ __forceinline__ float sigm(float x) { return 1.0f / (1.0f + expf(-x)); }
__device__ __forceinline__ unsigned lmask_lt() {
    unsigned m; asm("mov.u32 %0, %%lanemask_lt;" : "=r"(m)); return m;
}
__device__ __forceinline__ unsigned bytesum(ull v) {
    unsigned s = __dp4a((unsigned)v, 0x01010101u, 0u);
    return __dp4a((unsigned)(v >> 32), 0x01010101u, s);
}
// packed fp32x2 FMA (sm_103a)
__device__ __forceinline__ void fma2(ull& d, ull a, ull b) {
    asm("fma.rn.f32x2 %0, %1, %2, %0;" : "+l"(d) : "l"(a), "l"(b));
}
__device__ __forceinline__ ull pk2(float v) {
    ull r; asm("mov.b64 %0, {%1, %1};" : "=l"(r) : "f"(v)); return r;
}
union F4U { float4 f; ulonglong2 u; };

// Warp-level stable bitonic sort of 256 u64 items, 8 per lane.
__device__ __forceinline__ void warp_bitonic_256(ull v[8], int L) {
#pragma unroll
    for (int k = 2; k <= 256; k <<= 1) {
#pragma unroll
        for (int j = 128; j > 0; j >>= 1) {
            if (j >= k) continue;
            if (j >= 32) {
                int jr = j >> 5;
#pragma unroll
                for (int r = 0; r < 8; r++) {
                    if ((r & jr) == 0) {
                        int r2 = r | jr;
                        bool up = ((r & (k >> 5)) == 0);
                        ull a = v[r], b2 = v[r2];
                        if (up ? (a > b2) : (a < b2)) { v[r] = b2; v[r2] = a; }
                    }
                }
            } else {
#pragma unroll
                for (int r = 0; r < 8; r++) {
                    ull o = __shfl_xor_sync(0xffffffffu, v[r], j);
                    int i = r*32 + L;
                    bool up = ((i & k) == 0);
                    bool lower = ((L & j) == 0);
                    ull mn = (v[r] < o) ? v[r] : o;
                    ull mx = (v[r] < o) ? o : v[r];
                    v[r] = (up == lower) ? mn : mx;
                }
            }
        }
    }
}

// K1: stable sort along h for first 32 channels
__global__ __launch_bounds__(256) void k_colsort(const float* __restrict__ x) {
    __shared__ float tile[256][9];
    __shared__ unsigned char sidx[256][9];
    int bx = blockIdx.x;
    int wt = bx & 31, c = (bx >> 5) & 31, b = bx >> 10;
    int w0 = wt * 8, t = threadIdx.x;
    const float* src = x + (((b*64 + c)*256 + t)*256 + w0);
    float4 f0 = *(const float4*)src;
    float4 f1 = *(const float4*)(src + 4);
    tile[t][0]=f0.x; tile[t][1]=f0.y; tile[t][2]=f0.z; tile[t][3]=f0.w;
    tile[t][4]=f1.x; tile[t][5]=f1.y; tile[t][6]=f1.z; tile[t][7]=f1.w;
    __syncthreads();
    int w = t >> 5, L = t & 31;
    ull v[8];
#pragma unroll
    for (int r = 0; r < 8; r++) {
        int i = r*32 + L;
        v[r] = ((ull)fkey(tile[i][w]) << 8) | (unsigned)i;
    }
    warp_bitonic_256(v, L);
#pragma unroll
    for (int r = 0; r < 8; r++) {
        int n = r*32 + L;
        tile[n][w] = fdec((unsigned)(v[r] >> 8));
        sidx[n][w] = (unsigned char)(v[r] & 0xFF);
    }
    __syncthreads();
    float* dst = g_x + (((b*64 + c)*256 + t)*256 + w0);
    float4 o0, o1;
    o0.x=tile[t][0]; o0.y=tile[t][1]; o0.z=tile[t][2]; o0.w=tile[t][3];
    o1.x=tile[t][4]; o1.y=tile[t][5]; o1.z=tile[t][6]; o1.w=tile[t][7];
    *(float4*)dst = o0; *(float4*)(dst + 4) = o1;
    ull ib = 0;
#pragma unroll
    for (int q = 0; q < 8; q++) ib |= (ull)sidx[t][q] << (8*q);
    *(ull*)(g_idxh + (((b*32 + c)*256 + t)*256 + w0)) = ib;
}

// K2: stable sort along w
__global__ __launch_bounds__(256) void k_rowsort() {
    int t = threadIdx.x, w = t >> 5, L = t & 31;
    int rid = blockIdx.x*8 + w;
    int b = rid >> 13, c = (rid >> 8) & 31, hrow = rid & 255;
    float* base = g_x + (((b*64 + c)*256 + hrow)*256);
    ull v[8];
#pragma unroll
    for (int r = 0; r < 8; r++) {
        int i = r*32 + L;
        v[r] = ((ull)fkey(base[i]) << 8) | (unsigned)i;
    }
    warp_bitonic_256(v, L);
    unsigned char* di = g_idxw + ((size_t)((b*32 + c)*256 + hrow))*256;
#pragma unroll
    for (int r = 0; r < 8; r++) {
        int i = r*32 + L;
        base[i] = fdec((unsigned)(v[r] >> 8));
        di[i] = (unsigned char)(v[r] & 0xFF);
    }
}

// K3: qkv 1x1 conv GEMM — f32x2 packed FMA
__global__ __launch_bounds__(256, 2) void k_qkv(const float* __restrict__ wqkv, const float* __restrict__ x) {
    extern __shared__ char sm[];
    float* xs  = (float*)sm;            // [64][256]
    float* wsT = (float*)(sm + 65536);  // [64][68]
    int b = blockIdx.y;
    int p0 = blockIdx.x * 256, t = threadIdx.x;
    for (int m = t; m < 64*64; m += 256) {
        int c = m >> 6, q = m & 63;
        const float* src = (c < 32) ? (g_x + (b*64 + c)*NN + p0) : (x + (b*64 + c)*NN + p0);
        ((float4*)(xs + c*256))[q] = ((const float4*)src)[q];
    }
    int ob = (t >> 5) * 8, pb = (t & 31) * 4;
    for (int oc = 0; oc < 3; oc++) {
        __syncthreads();
        for (int m = t; m < 4096; m += 256)
            wsT[(m & 63)*68 + (m >> 6)] = wqkv[oc*4096 + m];
        __syncthreads();
        ull acc[8][4];
#pragma unroll
        for (int u = 0; u < 8; u++)
#pragma unroll
            for (int v = 0; v < 4; v++) acc[u][v] = 0ull;
#pragma unroll 4
        for (int c = 0; c < 64; c++) {
            F4U xa, xb;
            xa.f = *(const float4*)(xs + c*256 + pb);
            xb.f = *(const float4*)(xs + c*256 + pb + 128);
            float4 w0 = *(const float4*)(wsT + c*68 + ob);
            float4 w1 = *(const float4*)(wsT + c*68 + ob + 4);
#pragma unroll
            for (int u = 0; u < 4; u++) {
                float wu = (u == 0) ? w0.x : (u == 1) ? w0.y : (u == 2) ? w0.z : w0.w;
                ull wp = pk2(wu);
                fma2(acc[u][0], wp, xa.u.x); fma2(acc[u][1], wp, xa.u.y);
                fma2(acc[u][2], wp, xb.u.x); fma2(acc[u][3], wp, xb.u.y);
            }
#pragma unroll
            for (int u = 0; u < 4; u++) {
                float wu = (u == 0) ? w1.x : (u == 1) ? w1.y : (u == 2) ? w1.z : w1.w;
                ull wp = pk2(wu);
                fma2(acc[u+4][0], wp, xa.u.x); fma2(acc[u+4][1], wp, xa.u.y);
                fma2(acc[u+4][2], wp, xb.u.x); fma2(acc[u+4][3], wp, xb.u.y);
            }
        }
#pragma unroll
        for (int u = 0; u < 8; u++) {
            float* dst = g_qkv + ((size_t)(b*192 + oc*64 + ob + u))*NN + p0;
            F4U o0, o1;
            o0.u.x = acc[u][0]; o0.u.y = acc[u][1];
            o1.u.x = acc[u][2]; o1.u.y = acc[u][3];
            *(float4*)(dst + pb) = o0.f;
            *(float4*)(dst + pb + 128) = o1.f;
        }
    }
}

// K4: depthwise 3x3 — type A (c<64): q&k paired; type B: v -> keys + pass-1 hist
__global__ __launch_bounds__(256) void k_dwconv(const float* __restrict__ wdw, unsigned* __restrict__ K0,
                                                unsigned* __restrict__ cntA) {
    __shared__ float red[8][2];
    __shared__ unsigned vhist[256];
    int cx = blockIdx.x;
    int c = cx & 127, b = cx >> 7;
    int t = threadIdx.x;
    int i = blockIdx.y*4 + (t >> 6);
    int j0 = (t & 63) * 4;
    int p = i*256 + j0;

    if (c < 64) {
        const float* inq = g_qkv + (size_t)(b*192 + c)*NN;
        const float* ink = g_qkv + (size_t)(b*192 + 64 + c)*NN;
        float wq[9], wk[9];
#pragma unroll
        for (int q = 0; q < 9; q++) { wq[q] = wdw[c*9 + q]; wk[q] = wdw[(64 + c)*9 + q]; }
        float qa0=0.f,qa1=0.f,qa2=0.f,qa3=0.f, ka0=0.f,ka1=0.f,ka2=0.f,ka3=0.f;
#pragma unroll
        for (int ky = 0; ky < 3; ky++) {
            int ii = i + ky - 1;
            if (ii < 0 || ii > 255) continue;
            const float* rq = inq + ii*256;
            const float* rk = ink + ii*256;
            float4 cq = *(const float4*)(rq + j0);
            float lq = (j0 > 0)   ? rq[j0 - 1] : 0.0f;
            float rqv = (j0 < 252) ? rq[j0 + 4] : 0.0f;
            float w0 = wq[ky*3+0], w1 = wq[ky*3+1], w2 = wq[ky*3+2];
            qa0 += w0*lq   + w1*cq.x + w2*cq.y;
            qa1 += w0*cq.x + w1*cq.y + w2*cq.z;
            qa2 += w0*cq.y + w1*cq.z + w2*cq.w;
            qa3 += w0*cq.z + w1*cq.w + w2*rqv;
            float4 ck = *(const float4*)(rk + j0);
            float lk = (j0 > 0)   ? rk[j0 - 1] : 0.0f;
            float rkv = (j0 < 252) ? rk[j0 + 4] : 0.0f;
            float v0 = wk[ky*3+0], v1 = wk[ky*3+1], v2 = wk[ky*3+2];
            ka0 += v0*lk   + v1*ck.x + v2*ck.y;
            ka1 += v0*ck.x + v1*ck.y + v2*ck.z;
            ka2 += v0*ck.y + v1*ck.z + v2*ck.w;
            ka3 += v0*ck.z + v1*ck.w + v2*rkv;
        }
        float2* dst = ((float2*)g_dw) + (size_t)(b*64 + c)*NN + p;
        float4 s0; s0.x = qa0; s0.y = ka0; s0.z = qa1; s0.w = ka1;
        float4 s1; s1.x = qa2; s1.y = ka2; s1.z = qa3; s1.w = ka3;
        *(float4*)dst = s0;
        *(float4*)(dst + 2) = s1;
        float sq = qa0*qa0 + qa1*qa1 + qa2*qa2 + qa3*qa3;
        float sk = ka0*ka0 + ka1*ka1 + ka2*ka2 + ka3*ka3;
#pragma unroll
        for (int s = 16; s > 0; s >>= 1) {
            sq += __shfl_down_sync(0xffffffffu, sq, s);
            sk += __shfl_down_sync(0xffffffffu, sk, s);
        }
        if ((t & 31) == 0) { red[t >> 5][0] = sq; red[t >> 5][1] = sk; }
        __syncthreads();
        if (t == 0) {
            float s1s = 0.0f, s2s = 0.0f;
#pragma unroll
            for (int w2 = 0; w2 < 8; w2++) { s1s += red[w2][0]; s2s += red[w2][1]; }
            atomicAdd(&g_nq[b*64 + c], s1s);
            atomicAdd(&g_nk[b*64 + c], s2s);
        }
    } else {
        int vc = c - 64;
        const float* in = g_qkv + (size_t)(b*192 + 128 + vc)*NN;
        float wl[9];
#pragma unroll
        for (int q = 0; q < 9; q++) wl[q] = wdw[(128 + vc)*9 + q];
        vhist[t] = 0;
        __syncthreads();
        float a0 = 0.f, a1 = 0.f, a2 = 0.f, a3 = 0.f;
#pragma unroll
        for (int ky = 0; ky < 3; ky++) {
            int ii = i + ky - 1;
            if (ii < 0 || ii > 255) continue;
            const float* row = in + ii*256;
            float4 c4 = *(const float4*)(row + j0);
            float lf = (j0 > 0)   ? row[j0 - 1] : 0.0f;
            float rt = (j0 < 252) ? row[j0 + 4] : 0.0f;
            float w0 = wl[ky*3+0], w1 = wl[ky*3+1], w2 = wl[ky*3+2];
            a0 += w0*lf   + w1*c4.x + w2*c4.y;
            a1 += w0*c4.x + w1*c4.y + w2*c4.z;
            a2 += w0*c4.y + w1*c4.z + w2*c4.w;
            a3 += w0*c4.z + w1*c4.w + w2*rt;
        }
        int seg = b*64 + vc;
        unsigned k0 = fkey(a0), k1 = fkey(a1), k2 = fkey(a2), k3 = fkey(a3);
        uint4 kk; kk.x = k0; kk.y = k1; kk.z = k2; kk.w = k3;
        *(uint4*)(K0 + (size_t)seg*NN + p) = kk;
        atomicAdd(&vhist[(k0 >> 8) & 255u], 1u);
        atomicAdd(&vhist[(k1 >> 8) & 255u], 1u);
        atomicAdd(&vhist[(k2 >> 8) & 255u], 1u);
        atomicAdd(&vhist[(k3 >> 8) & 255u], 1u);
        __syncthreads();
        unsigned v = vhist[t];
        if (v) {
            int blk = blockIdx.y >> 1;   // 1024 px per dwconv block -> 2048-item sort block = y/2
            atomicAdd(&cntA[(seg*NBLK + blk)*256 + t], v);
        }
    }
}

// K5: per-segment scan of counts (NBLK sub-blocks) -> within-segment offsets
__global__ __launch_bounds__(256) void k_scan(unsigned* __restrict__ cnt) {
    __shared__ unsigned cl[NBLK][256];
    __shared__ unsigned scn[256];
    int seg = blockIdx.x, t = threadIdx.x;
    for (int blk = 0; blk < NBLK; blk++)
        cl[blk][t] = cnt[(seg*NBLK + blk)*256 + t];
    __syncthreads();
    unsigned s = 0;
    for (int blk = 0; blk < NBLK; blk++) s += cl[blk][t];
    unsigned mytot = s;
    scn[t] = s;
    __syncthreads();
    for (int off = 1; off < 256; off <<= 1) {
        unsigned v = scn[t];
        unsigned add = (t >= off) ? scn[t - off] : 0;
        __syncthreads();
        scn[t] = v + add;
        __syncthreads();
    }
    unsigned run = scn[t] - mytot;
    for (int blk = 0; blk < NBLK; blk++) {
        cnt[(seg*NBLK + blk)*256 + t] = run;
        run += cl[blk][t];
    }
}

// K6: stable scatter (8 rounds, 2048-item blocks) — proven ranking logic
__global__ __launch_bounds__(256) void k_scatter(const unsigned* __restrict__ srcK,
                                                 const unsigned short* __restrict__ srcP,
                                                 unsigned* __restrict__ dstK,
                                                 unsigned short* __restrict__ dstP,
                                                 int shift,
                                                 const unsigned* __restrict__ cntCur,
                                                 unsigned* __restrict__ cntNext, int nextshift,
                                                 float* __restrict__ vout,
                                                 unsigned short* __restrict__ iout) {
    extern __shared__ char sm[];
    unsigned* stageK        = (unsigned*)sm;                    // 8192
    unsigned short* stageP  = (unsigned short*)(sm + 8192);     // 4096
    unsigned* h2            = (unsigned*)(sm + 12288);          // 32768 (NBLK*256)
    ull* wcnt64             = (ull*)(sm + 45056);               // 2048
    unsigned* scn           = (unsigned*)(sm + 47104);          // 1024
    unsigned* offsC         = (unsigned*)(sm + 48128);          // 1024
    unsigned short* rankOf  = (unsigned short*)(sm + 49152);    // 4096
    unsigned short* runbase = (unsigned short*)(sm + 53248);    // 512
    unsigned short* startLoc= (unsigned short*)(sm + 53760);    // 512

    int t = threadIdx.x;
    int w = t >> 5;
    unsigned ltm = lmask_lt();
    int base = blockIdx.x * SBLK;
    int seg = base >> 16;
    bool doNext = (cntNext != nullptr);
    bool isFinal = (vout != nullptr);

    runbase[t] = 0;
    offsC[t] = cntCur[blockIdx.x*256 + t];
    if (doNext)
        for (int m = t; m < NBLK*256; m += 256) h2[m] = 0;

    unsigned key[8];
    unsigned short pos[8];
#pragma unroll
    for (int r = 0; r < 8; r++) key[r] = srcK[base + r*256 + t];
    if (srcP) {
#pragma unroll
        for (int r = 0; r < 8; r++) pos[r] = srcP[base + r*256 + t];
    } else {
#pragma unroll
        for (int r = 0; r < 8; r++) pos[r] = (unsigned short)((base + r*256 + t) & 65535);
    }

    ull wmask = (1ull << (8*w)) - 1ull;
    for (int r = 0; r < 8; r++) {
        wcnt64[t] = 0ull;
        __syncthreads();
        unsigned d = (key[r] >> shift) & 255u;
        unsigned mask = __match_any_sync(0xffffffffu, d);
        unsigned lr = __popc(mask & ltm);
        if (lr == 0)
            ((unsigned char*)&wcnt64[d])[w] = (unsigned char)__popc(mask);
        __syncthreads();
        ull cd = wcnt64[d];
        ull ct = wcnt64[t];
        rankOf[r*256 + t] = (unsigned short)((unsigned)runbase[d] + bytesum(cd & wmask) + lr);
        __syncthreads();
        runbase[t] = (unsigned short)((unsigned)runbase[t] + bytesum(ct));
    }
    __syncthreads();
    unsigned mycnt = runbase[t];
    scn[t] = mycnt;
    __syncthreads();
    for (int off = 1; off < 256; off <<= 1) {
        unsigned v = scn[t];
        unsigned add = (t >= off) ? scn[t - off] : 0;
        __syncthreads();
        scn[t] = v + add;
        __syncthreads();
    }
    startLoc[t] = (unsigned short)(scn[t] - mycnt);
    __syncthreads();
#pragma unroll
    for (int r = 0; r < 8; r++) {
        unsigned d = (key[r] >> shift) & 255u;
        unsigned rank = rankOf[r*256 + t];
        unsigned sl = startLoc[d];
        stageK[sl + rank] = key[r];
        stageP[sl + rank] = pos[r];
        if (doNext) {
            unsigned ds = offsC[d] + rank;
            unsigned d2 = (key[r] >> nextshift) & 255u;
            atomicAdd(&h2[(ds >> 11)*256 + d2], 1u);
        }
    }
    __syncthreads();
    unsigned segbase = (unsigned)seg << 16;
    if (!isFinal) {
#pragma unroll
        for (int r = 0; r < 8; r++) {
            int j = r*256 + t;
            unsigned k2 = stageK[j];
            unsigned d = (k2 >> shift) & 255u;
            unsigned dsti = segbase + offsC[d] + (unsigned)j - startLoc[d];
            dstK[dsti] = k2;
            dstP[dsti] = stageP[j];
        }
    } else {
#pragma unroll
        for (int r = 0; r < 8; r++) {
            int j = r*256 + t;
            unsigned k2 = stageK[j];
            unsigned d = (k2 >> shift) & 255u;
            unsigned dsti = segbase + offsC[d] + (unsigned)j - startLoc[d];
            vout[dsti] = fdec(k2);
            iout[dsti] = stageP[j];
        }
    }
    if (doNext) {
        __syncthreads();
        for (int m = t; m < NBLK*256; m += 256) {
            unsigned v = h2[m];
            if (v) atomicAdd(&cntNext[(seg*NBLK + (m >> 8))*256 + (m & 255)], v);
        }
    }
}

// K7: raw 8x8 Gram per (b,head) — float2 gather; cross-warp smem combine
__global__ __launch_bounds__(256) void k_attn(const unsigned short* __restrict__ iall) {
    __shared__ float wsum[8][64];
    int bh = blockIdx.x; int b = bh >> 3, h = bh & 7;
    const float2* qk = ((const float2*)g_dw) + (size_t)(b*64 + h*8)*NN;
    const unsigned short* ip = iall + (size_t)(b*64 + h*8)*NN;
    float acc[64];
#pragma unroll
    for (int m = 0; m < 64; m++) acc[m] = 0.0f;
    int i0 = blockIdx.y * 4096;
    for (int i = i0 + threadIdx.x; i < i0 + 4096; i += 256) {
        unsigned id[8]; float qv[8], kv[8];
#pragma unroll
        for (int c = 0; c < 8; c++) id[c] = ip[c*NN + i];
#pragma unroll
        for (int c = 0; c < 8; c++) {
            float2 p = qk[(size_t)c*NN + id[c]];
            qv[c] = p.x; kv[c] = p.y;
        }
#pragma unroll
        for (int c = 0; c < 8; c++)
#pragma unroll
            for (int d = 0; d < 8; d++) acc[c*8+d] += qv[c]*kv[d];
    }
#pragma unroll
    for (int m = 0; m < 64; m++) {
#pragma unroll
        for (int s = 16; s > 0; s >>= 1)
            acc[m] += __shfl_down_sync(0xffffffffu, acc[m], s);
    }
    int w = threadIdx.x >> 5;
    if ((threadIdx.x & 31) == 0)
#pragma unroll
        for (int m = 0; m < 64; m++) wsum[w][m] = acc[m];
    __syncthreads();
    if (threadIdx.x < 64) {
        float s = 0.0f;
#pragma unroll
        for (int w2 = 0; w2 < 8; w2++) s += wsum[w2][threadIdx.x];
        atomicAdd(&g_attnraw[bh*64 + threadIdx.x], s);
    }
}

// K8: normalize + temperature + softmax
__global__ __launch_bounds__(512) void k_softmax(const float* __restrict__ temp) {
    int t = threadIdx.x;
    int b = t >> 6, h = (t >> 3) & 7, c = t & 7;
    int bh = b*8 + h;
    float nq = fmaxf(sqrtf(g_nq[b*64 + h*8 + c]), 1e-12f);
    float tp = temp[h];
    float a[8];
    float mx = -FLT_MAX;
#pragma unroll
    for (int d = 0; d < 8; d++) {
        float nk = fmaxf(sqrtf(g_nk[b*64 + h*8 + d]), 1e-12f);
        a[d] = g_attnraw[bh*64 + c*8 + d] / (nq*nk) * tp;
        mx = fmaxf(mx, a[d]);
    }
    float s = 0.0f;
#pragma unroll
    for (int d = 0; d < 8; d++) { a[d] = expf(a[d] - mx); s += a[d]; }
    float inv = 1.0f / s;
#pragma unroll
    for (int d = 0; d < 8; d++) g_attn[bh*64 + c*8 + d] = a[d]*inv;
}

// K9: out = attn @ v_s, scattered back; fused per-channel sum/max
__global__ __launch_bounds__(256) void k_av(const float* __restrict__ vall,
                                            const unsigned short* __restrict__ iall) {
    int bh = blockIdx.y; int b = bh >> 3, h = bh & 7;
    __shared__ float a[64];
    __shared__ float redS[8][8];
    __shared__ unsigned redM[8][8];
    if (threadIdx.x < 64) a[threadIdx.x] = g_attn[bh*64 + threadIdx.x];
    __syncthreads();
    int n = blockIdx.x*256 + threadIdx.x;
    int base = (b*64 + h*8)*NN;
    float v[8]; unsigned id[8];
#pragma unroll
    for (int d = 0; d < 8; d++) {
        v[d] = vall[base + d*NN + n];
        id[d] = iall[base + d*NN + n];
    }
    int w = threadIdx.x >> 5, lane = threadIdx.x & 31;
#pragma unroll
    for (int c = 0; c < 8; c++) {
        float s = 0.0f;
#pragma unroll
        for (int d = 0; d < 8; d++) s += a[c*8+d]*v[d];
        g_out[base + c*NN + id[c]] = s;
        float ssum = s;
        unsigned smax = fkey(s);
#pragma unroll
        for (int sh = 16; sh > 0; sh >>= 1) {
            ssum += __shfl_down_sync(0xffffffffu, ssum, sh);
            smax = max(smax, __shfl_down_sync(0xffffffffu, smax, sh));
        }
        if (lane == 0) { redS[c][w] = ssum; redM[c][w] = smax; }
    }
    __syncthreads();
    if (threadIdx.x < 8) {
        int c = threadIdx.x;
        float s = 0.0f; unsigned m = 0;
#pragma unroll
        for (int w2 = 0; w2 < 8; w2++) { s += redS[c][w2]; m = max(m, redM[c][w2]); }
        atomicAdd(&g_chsum[b*64 + h*8 + c], s);
        atomicMax(&g_chmaxu[b*64 + h*8 + c], m);
    }
}

// K10: channel attention
__global__ __launch_bounds__(64) void k_ca(const float* __restrict__ wfc1, const float* __restrict__ wfc2) {
    int b = blockIdx.x, c = threadIdx.x;
    __shared__ float mv[64], xv[64];
    mv[c] = g_chsum[b*64 + c] * (1.0f/65536.0f);
    xv[c] = fdec(g_chmaxu[b*64 + c]);
    __syncthreads();
    float r1[4], r2[4];
#pragma unroll
    for (int j = 0; j < 4; j++) {
        float s1 = 0.0f, s2 = 0.0f;
        for (int cc = 0; cc < 64; cc++) {
            float w = wfc1[j*64 + cc];
            s1 += mv[cc]*w; s2 += xv[cc]*w;
        }
        r1[j] = s1 * sigm(s1);
        r2[j] = s2 * sigm(s2);
    }
    float t1 = 0.0f, t2 = 0.0f;
#pragma unroll
    for (int j = 0; j < 4; j++) { t1 += r1[j]*wfc2[c*4 + j]; t2 += r2[j]*wfc2[c*4 + j]; }
    g_ca[b*64 + c] = sigm(t1) + sigm(t2);
}

// K11: spatial stats
__global__ __launch_bounds__(256) void k_sp() {
    int b = blockIdx.y;
    int n = blockIdx.x*256 + threadIdx.x;
    __shared__ float cas[64];
    if (threadIdx.x < 64) cas[threadIdx.x] = g_ca[b*64 + threadIdx.x];
    __syncthreads();
    float s = 0.0f, mx = -FLT_MAX, mn = FLT_MAX;
    for (int c = 0; c < 64; c++) {
        float v = g_out[(b*64 + c)*NN + n] * cas[c];
        s += v; mx = fmaxf(mx, v); mn = fminf(mn, v);
    }
    g_sp[(b*4 + 0)*NN + n] = s * (1.0f/64.0f);
    g_sp[(b*4 + 1)*NN + n] = mx;
    g_sp[(b*4 + 2)*NN + n] = mn;
    g_sp[(b*4 + 3)*NN + n] = s;
}

// K12: 7x7 conv (4->1) + silu + 1x1 + sigmoid
__global__ __launch_bounds__(256) void k_sa(const float* __restrict__ wsp1, const float* __restrict__ bsp1,
                                            const float* __restrict__ wsp2, const float* __restrict__ bsp2) {
    __shared__ float tile[4][22][22];
    __shared__ float ws[196];
    int b = blockIdx.z;
    int y0 = blockIdx.y*16, x0 = blockIdx.x*16;
    int tx = threadIdx.x & 15, ty = threadIdx.x >> 4;
    int tid = threadIdx.x;
    if (tid < 196) ws[tid] = wsp1[tid];
    for (int m = tid; m < 4*484; m += 256) {
        int ic = m / 484, rr = m % 484;
        int iy = rr / 22, ix = rr % 22;
        int gy = y0 + iy - 3, gx = x0 + ix - 3;
        tile[ic][iy][ix] = (gy >= 0 && gy < 256 && gx >= 0 && gx < 256)
                           ? g_sp[(b*4 + ic)*NN + gy*256 + gx] : 0.0f;
    }
    __syncthreads();
    float acc = 0.0f;
#pragma unroll
    for (int ic = 0; ic < 4; ic++)
#pragma unroll
        for (int ky = 0; ky < 7; ky++)
#pragma unroll
            for (int kx = 0; kx < 7; kx++)
                acc += ws[ic*49 + ky*7 + kx] * tile[ic][ty+ky][tx+kx];
    float s = acc + bsp1[0];
    float sl = s * sigm(s);
    float t2 = wsp2[0]*sl + bsp2[0];
    g_sa[b*NN + (y0+ty)*256 + x0+tx] = sigm(t2);
}

// K13: projection GEMM + ca*sa scaling + inverse permutations (c<32)
__global__ __launch_bounds__(256) void k_proj(const float* __restrict__ wproj, float* __restrict__ out) {
    __shared__ float xs[64][128];
    __shared__ float wp[64][64];
    __shared__ float sas[128];
    __shared__ float cas[64];
    int b = blockIdx.y;
    int p0 = blockIdx.x * 128, t = threadIdx.x;
    if (t < 64) cas[t] = g_ca[b*64 + t];
    if (t < 128) sas[t] = g_sa[b*NN + p0 + t];
    __syncthreads();
    for (int m = t; m < 64*128; m += 256) {
        int c = m >> 7, px = m & 127;
        xs[c][px] = g_out[(b*64 + c)*NN + p0 + px] * cas[c];
    }
    for (int m = t; m < 4096; m += 256) {
        int o = m >> 6, c = m & 63;
        wp[o][c] = wproj[o*64 + c];
    }
    __syncthreads();
    int ob = (t >> 5) * 8, pb = (t & 31) * 4;
    float acc[8][4];
#pragma unroll
    for (int u = 0; u < 8; u++)
#pragma unroll
        for (int v = 0; v < 4; v++) acc[u][v] = 0.0f;
#pragma unroll 4
    for (int c0 = 0; c0 < 64; c0 += 4) {
        float4 wv[8];
#pragma unroll
        for (int u = 0; u < 8; u++) wv[u] = *(const float4*)&wp[ob + u][c0];
#pragma unroll
        for (int cc = 0; cc < 4; cc++) {
            float4 xv = *(const float4*)&xs[c0 + cc][pb];
#pragma unroll
            for (int u = 0; u < 8; u++) {
                float wu = (cc == 0) ? wv[u].x : (cc == 1) ? wv[u].y : (cc == 2) ? wv[u].z : wv[u].w;
                acc[u][0] += wu*xv.x; acc[u][1] += wu*xv.y;
                acc[u][2] += wu*xv.z; acc[u][3] += wu*xv.w;
            }
        }
    }
#pragma unroll
    for (int u = 0; u < 8; u++) {
        int o = ob + u;
        if (o >= 32) {
#pragma unroll
            for (int v = 0; v < 4; v++)
                out[(b*64 + o)*NN + p0 + pb + v] = acc[u][v] * sas[pb + v];
        } else {
            int ibase = (b*32 + o) * NN;
#pragma unroll
            for (int v = 0; v < 4; v++) {
                int n = p0 + pb + v;
                int q = n >> 8, p = n & 255;
                int j = (int)g_idxw[ibase + q*256 + p];
                int r = (int)g_idxh[ibase + q*256 + j];
                out[(b*64 + o)*NN + r*256 + j] = acc[u][v] * sas[pb + v];
            }
        }
    }
}

extern "C" void kernel_launch(void* const* d_in, const int* in_sizes, int n_in,
                              void* d_out, int out_size) {
    const float* x     = (const float*)d_in[0];
    const float* temp  = (const float*)d_in[1];
    const float* wqkv  = (const float*)d_in[2];
    const float* wdw   = (const float*)d_in[3];
    const float* wfc1  = (const float*)d_in[4];
    const float* wfc2  = (const float*)d_in[5];
    const float* wsp1  = (const float*)d_in[6];
    const float* bsp1  = (const float*)d_in[7];
    const float* wsp2  = (const float*)d_in[8];
    const float* bsp2  = (const float*)d_in[9];
    const float* wproj = (const float*)d_in[10];
    float* out = (float*)d_out;

    cudaFuncSetAttribute(k_scatter, cudaFuncAttributeMaxDynamicSharedMemorySize, 54272);
    cudaFuncSetAttribute(k_qkv, cudaFuncAttributeMaxDynamicSharedMemorySize, 82944);

    void *pS0, *pS1, *pattn, *pnq, *pnk, *pchs, *pchm, *pA, *pB, *pC, *pvx, *pqkv;
    cudaGetSymbolAddress(&pS0, g_keys0);
    cudaGetSymbolAddress(&pS1, g_keys1);
    cudaGetSymbolAddress(&pattn, g_attnraw);
    cudaGetSymbolAddress(&pnq, g_nq);
    cudaGetSymbolAddress(&pnk, g_nk);
    cudaGetSymbolAddress(&pchs, g_chsum);
    cudaGetSymbolAddress(&pchm, g_chmaxu);
    cudaGetSymbolAddress(&pA, g_cntA);
    cudaGetSymbolAddress(&pB, g_cntB);
    cudaGetSymbolAddress(&pC, g_cntC);
    cudaGetSymbolAddress(&pvx, g_x);
    cudaGetSymbolAddress(&pqkv, g_qkv);
    unsigned* K0 = (unsigned*)pS0;
    unsigned short* P0 = (unsigned short*)((unsigned*)pS0 + TOT);
    unsigned* K1 = (unsigned*)pS1;
    unsigned short* P1 = (unsigned short*)((unsigned*)pS1 + TOT);
    unsigned* cntA = (unsigned*)pA;
    unsigned* cntB = (unsigned*)pB;
    unsigned* cntC = (unsigned*)pC;
    float* vall = (float*)pvx;
    unsigned short* iall = (unsigned short*)pqkv;
    const size_t CNT_BYTES = 512ull*NBLK*256*4;

    cudaMemsetAsync(pnq, 0, sizeof(float)*BB*CC);
    cudaMemsetAsync(pnk, 0, sizeof(float)*BB*CC);
    cudaMemsetAsync(pchs, 0, sizeof(float)*BB*CC);
    cudaMemsetAsync(pchm, 0, sizeof(unsigned)*BB*CC);
    cudaMemsetAsync(pattn, 0, sizeof(float)*BB*HEADS*64);
    cudaMemsetAsync(cntA, 0, CNT_BYTES);
    cudaMemsetAsync(cntB, 0, CNT_BYTES);
    cudaMemsetAsync(cntC, 0, CNT_BYTES);

    k_colsort<<<8192, 256>>>(x);
    k_rowsort<<<8192, 256>>>();
    k_qkv<<<dim3(NN/256, BB), 256, 82944>>>(wqkv, x);
    k_dwconv<<<dim3(BB*128, 64), 256>>>(wdw, K0, cntA);

    // segmented radix sort: 3 passes on key bits [8,32); 2048-item scatter blocks
    k_scan<<<512, 256>>>(cntA);
    k_scatter<<<512*NBLK, 256, 54272>>>(K0, nullptr, K1, P1, 8, cntA, cntB, 16, nullptr, nullptr);
    k_scan<<<512, 256>>>(cntB);
    k_scatter<<<512*NBLK, 256, 54272>>>(K1, P1, K0, P0, 16, cntB, cntC, 24, nullptr, nullptr);
    k_scan<<<512, 256>>>(cntC);
    k_scatter<<<512*NBLK, 256, 54272>>>(K0, P0, nullptr, nullptr, 24, cntC, nullptr, 0, vall, iall);

    k_attn<<<dim3(BB*HEADS, 16), 256>>>(iall);
    k_softmax<<<1, 512>>>(temp);
    k_av<<<dim3(NN/256, BB*HEADS), 256>>>(vall, iall);
    k_ca<<<BB, 64>>>(wfc1, wfc2);
    k_sp<<<dim3(NN/256, BB), 256>>>();
    k_sa<<<dim3(16, 16, BB), 256>>>(wsp1, bsp1, wsp2, bsp2);
    k_proj<<<dim3(NN/128, BB), 256>>>(wproj, out);
}

// round 13
// speedup vs baseline: 1.0306x; 1.0306x over previous
#include <cuda_runtime.h>
#include <math.h>
#include <float.h>

#define BB 8
#define CC 64
#define NN 65536
#define HEADS 8
#define C3 192
#define TOT (BB*CC*NN)
typedef unsigned long long ull;

// ------------------- static scratch -------------------
__device__ __align__(256) float g_x[TOT];                 // sorted x; later v_s floats
__device__ __align__(256) float g_qkv[BB*C3*NN];          // qkv; later id u16 array
__device__ __align__(256) float g_dw[BB*128*NN];          // interleaved (q,k) float2
__device__ __align__(256) ull g_keys0[TOT];               // K0 (u32) + P0 (u16)
__device__ __align__(256) ull g_keys1[TOT];               // K1 + P1
__device__ __align__(256) float g_out[TOT];
__device__ unsigned g_cntA[512*16*256];
__device__ unsigned g_cntB[512*16*256];
__device__ unsigned g_cntC[512*16*256];
__device__ unsigned char g_idxh[BB*32*NN];
__device__ unsigned char g_idxw[BB*32*NN];
__device__ float g_nq[BB*CC], g_nk[BB*CC];
__device__ float g_attnraw[BB*HEADS*64];
__device__ float g_attn[BB*HEADS*64];
__device__ float g_chsum[BB*CC];
__device__ unsigned g_chmaxu[BB*CC];
__device__ float g_ca[BB*CC];
__device__ float g_sp[BB*4*NN];
__device__ float g_sa[BB*NN];

// ------------------- helpers -------------------
__device__ __forceinline__ unsigned fkey(float f) {
    unsigned u = __float_as_uint(f);
    return (u & 0x80000000u) ? ~u : (u | 0x80000000u);
}
__device__ __forceinline__ float fdec(unsigned k) {
    return __uint_as_float((k & 0x80000000u) ? (k ^ 0x80000000u) : ~k);
}
__device__ __forceinline__ float sigm(float x) { return 1.0f / (1.0f + expf(-x)); }
__device__ __forceinline__ unsigned lmask_lt() {
    unsigned m; asm("mov.u32 %0, %%lanemask_lt;" : "=r"(m)); return m;
}
__device__ __forceinline__ unsigned bytesum(ull v) {
    unsigned s = __dp4a((unsigned)v, 0x01010101u, 0u);
    return __dp4a((unsigned)(v >> 32), 0x01010101u, s);
}
// packed fp32x2 FMA (sm_103a)
__device__ __forceinline__ void fma2(ull& d, ull a, ull b) {
    asm("fma.rn.f32x2 %0, %1, %2, %0;" : "+l"(d) : "l"(a), "l"(b));
}
__device__ __forceinline__ ull pk2(float v) {
    ull r; asm("mov.b64 %0, {%1, %1};" : "=l"(r) : "f"(v)); return r;
}
union F4U { float4 f; ulonglong2 u; };

// Warp-level stable bitonic sort of 256 u64 items, 8 per lane.
__device__ __forceinline__ void warp_bitonic_256(ull v[8], int L) {
#pragma unroll
    for (int k = 2; k <= 256; k <<= 1) {
#pragma unroll
        for (int j = 128; j > 0; j >>= 1) {
            if (j >= k) continue;
            if (j >= 32) {
                int jr = j >> 5;
#pragma unroll
                for (int r = 0; r < 8; r++) {
                    if ((r & jr) == 0) {
                        int r2 = r | jr;
                        bool up = ((r & (k >> 5)) == 0);
                        ull a = v[r], b2 = v[r2];
                        if (up ? (a > b2) : (a < b2)) { v[r] = b2; v[r2] = a; }
                    }
                }
            } else {
#pragma unroll
                for (int r = 0; r < 8; r++) {
                    ull o = __shfl_xor_sync(0xffffffffu, v[r], j);
                    int i = r*32 + L;
                    bool up = ((i & k) == 0);
                    bool lower = ((L & j) == 0);
                    ull mn = (v[r] < o) ? v[r] : o;
                    ull mx = (v[r] < o) ? o : v[r];
                    v[r] = (up == lower) ? mn : mx;
                }
            }
        }
    }
}

// K1: stable sort along h for first 32 channels
__global__ __launch_bounds__(256) void k_colsort(const float* __restrict__ x) {
    __shared__ float tile[256][9];
    __shared__ unsigned char sidx[256][9];
    int bx = blockIdx.x;
    int wt = bx & 31, c = (bx >> 5) & 31, b = bx >> 10;
    int w0 = wt * 8, t = threadIdx.x;
    const float* src = x + (((b*64 + c)*256 + t)*256 + w0);
    float4 f0 = *(const float4*)src;
    float4 f1 = *(const float4*)(src + 4);
    tile[t][0]=f0.x; tile[t][1]=f0.y; tile[t][2]=f0.z; tile[t][3]=f0.w;
    tile[t][4]=f1.x; tile[t][5]=f1.y; tile[t][6]=f1.z; tile[t][7]=f1.w;
    __syncthreads();
    int w = t >> 5, L = t & 31;
    ull v[8];
#pragma unroll
    for (int r = 0; r < 8; r++) {
        int i = r*32 + L;
        v[r] = ((ull)fkey(tile[i][w]) << 8) | (unsigned)i;
    }
    warp_bitonic_256(v, L);
#pragma unroll
    for (int r = 0; r < 8; r++) {
        int n = r*32 + L;
        tile[n][w] = fdec((unsigned)(v[r] >> 8));
        sidx[n][w] = (unsigned char)(v[r] & 0xFF);
    }
    __syncthreads();
    float* dst = g_x + (((b*64 + c)*256 + t)*256 + w0);
    float4 o0, o1;
    o0.x=tile[t][0]; o0.y=tile[t][1]; o0.z=tile[t][2]; o0.w=tile[t][3];
    o1.x=tile[t][4]; o1.y=tile[t][5]; o1.z=tile[t][6]; o1.w=tile[t][7];
    *(float4*)dst = o0; *(float4*)(dst + 4) = o1;
    ull ib = 0;
#pragma unroll
    for (int q = 0; q < 8; q++) ib |= (ull)sidx[t][q] << (8*q);
    *(ull*)(g_idxh + (((b*32 + c)*256 + t)*256 + w0)) = ib;
}

// K2: stable sort along w
__global__ __launch_bounds__(256) void k_rowsort() {
    int t = threadIdx.x, w = t >> 5, L = t & 31;
    int rid = blockIdx.x*8 + w;
    int b = rid >> 13, c = (rid >> 8) & 31, hrow = rid & 255;
    float* base = g_x + (((b*64 + c)*256 + hrow)*256);
    ull v[8];
#pragma unroll
    for (int r = 0; r < 8; r++) {
        int i = r*32 + L;
        v[r] = ((ull)fkey(base[i]) << 8) | (unsigned)i;
    }
    warp_bitonic_256(v, L);
    unsigned char* di = g_idxw + ((size_t)((b*32 + c)*256 + hrow))*256;
#pragma unroll
    for (int r = 0; r < 8; r++) {
        int i = r*32 + L;
        base[i] = fdec((unsigned)(v[r] >> 8));
        di[i] = (unsigned char)(v[r] & 0xFF);
    }
}

// K3: qkv 1x1 conv GEMM — f32x2 packed FMA
__global__ __launch_bounds__(256, 2) void k_qkv(const float* __restrict__ wqkv, const float* __restrict__ x) {
    extern __shared__ char sm[];
    float* xs  = (float*)sm;            // [64][256]
    float* wsT = (float*)(sm + 65536);  // [64][68]
    int b = blockIdx.y;
    int p0 = blockIdx.x * 256, t = threadIdx.x;
    for (int m = t; m < 64*64; m += 256) {
        int c = m >> 6, q = m & 63;
        const float* src = (c < 32) ? (g_x + (b*64 + c)*NN + p0) : (x + (b*64 + c)*NN + p0);
        ((float4*)(xs + c*256))[q] = ((const float4*)src)[q];
    }
    int ob = (t >> 5) * 8, pb = (t & 31) * 4;
    for (int oc = 0; oc < 3; oc++) {
        __syncthreads();
        for (int m = t; m < 4096; m += 256)
            wsT[(m & 63)*68 + (m >> 6)] = wqkv[oc*4096 + m];
        __syncthreads();
        ull acc[8][4];
#pragma unroll
        for (int u = 0; u < 8; u++)
#pragma unroll
            for (int v = 0; v < 4; v++) acc[u][v] = 0ull;
#pragma unroll 4
        for (int c = 0; c < 64; c++) {
            F4U xa, xb;
            xa.f = *(const float4*)(xs + c*256 + pb);
            xb.f = *(const float4*)(xs + c*256 + pb + 128);
            float4 w0 = *(const float4*)(wsT + c*68 + ob);
            float4 w1 = *(const float4*)(wsT + c*68 + ob + 4);
#pragma unroll
            for (int u = 0; u < 4; u++) {
                float wu = (u == 0) ? w0.x : (u == 1) ? w0.y : (u == 2) ? w0.z : w0.w;
                ull wp = pk2(wu);
                fma2(acc[u][0], wp, xa.u.x); fma2(acc[u][1], wp, xa.u.y);
                fma2(acc[u][2], wp, xb.u.x); fma2(acc[u][3], wp, xb.u.y);
            }
#pragma unroll
            for (int u = 0; u < 4; u++) {
                float wu = (u == 0) ? w1.x : (u == 1) ? w1.y : (u == 2) ? w1.z : w1.w;
                ull wp = pk2(wu);
                fma2(acc[u+4][0], wp, xa.u.x); fma2(acc[u+4][1], wp, xa.u.y);
                fma2(acc[u+4][2], wp, xb.u.x); fma2(acc[u+4][3], wp, xb.u.y);
            }
        }
#pragma unroll
        for (int u = 0; u < 8; u++) {
            float* dst = g_qkv + ((size_t)(b*192 + oc*64 + ob + u))*NN + p0;
            F4U o0, o1;
            o0.u.x = acc[u][0]; o0.u.y = acc[u][1];
            o1.u.x = acc[u][2]; o1.u.y = acc[u][3];
            *(float4*)(dst + pb) = o0.f;
            *(float4*)(dst + pb + 128) = o1.f;
        }
    }
}

// K4: depthwise 3x3 — type A (c<64): q&k paired; type B: v -> keys + pass-1 hist
__global__ __launch_bounds__(256) void k_dwconv(const float* __restrict__ wdw, unsigned* __restrict__ K0,
                                                unsigned* __restrict__ cntA) {
    __shared__ float red[8][2];
    __shared__ unsigned vhist[256];
    int cx = blockIdx.x;
    int c = cx & 127, b = cx >> 7;
    int t = threadIdx.x;
    int i = blockIdx.y*4 + (t >> 6);
    int j0 = (t & 63) * 4;
    int p = i*256 + j0;

    if (c < 64) {
        const float* inq = g_qkv + (size_t)(b*192 + c)*NN;
        const float* ink = g_qkv + (size_t)(b*192 + 64 + c)*NN;
        float wq[9], wk[9];
#pragma unroll
        for (int q = 0; q < 9; q++) { wq[q] = wdw[c*9 + q]; wk[q] = wdw[(64 + c)*9 + q]; }
        float qa0=0.f,qa1=0.f,qa2=0.f,qa3=0.f, ka0=0.f,ka1=0.f,ka2=0.f,ka3=0.f;
#pragma unroll
        for (int ky = 0; ky < 3; ky++) {
            int ii = i + ky - 1;
            if (ii < 0 || ii > 255) continue;
            const float* rq = inq + ii*256;
            const float* rk = ink + ii*256;
            float4 cq = *(const float4*)(rq + j0);
            float lq = (j0 > 0)   ? rq[j0 - 1] : 0.0f;
            float rqv = (j0 < 252) ? rq[j0 + 4] : 0.0f;
            float w0 = wq[ky*3+0], w1 = wq[ky*3+1], w2 = wq[ky*3+2];
            qa0 += w0*lq   + w1*cq.x + w2*cq.y;
            qa1 += w0*cq.x + w1*cq.y + w2*cq.z;
            qa2 += w0*cq.y + w1*cq.z + w2*cq.w;
            qa3 += w0*cq.z + w1*cq.w + w2*rqv;
            float4 ck = *(const float4*)(rk + j0);
            float lk = (j0 > 0)   ? rk[j0 - 1] : 0.0f;
            float rkv = (j0 < 252) ? rk[j0 + 4] : 0.0f;
            float v0 = wk[ky*3+0], v1 = wk[ky*3+1], v2 = wk[ky*3+2];
            ka0 += v0*lk   + v1*ck.x + v2*ck.y;
            ka1 += v0*ck.x + v1*ck.y + v2*ck.z;
            ka2 += v0*ck.y + v1*ck.z + v2*ck.w;
            ka3 += v0*ck.z + v1*ck.w + v2*rkv;
        }
        float2* dst = ((float2*)g_dw) + (size_t)(b*64 + c)*NN + p;
        float4 s0; s0.x = qa0; s0.y = ka0; s0.z = qa1; s0.w = ka1;
        float4 s1; s1.x = qa2; s1.y = ka2; s1.z = qa3; s1.w = ka3;
        *(float4*)dst = s0;
        *(float4*)(dst + 2) = s1;
        float sq = qa0*qa0 + qa1*qa1 + qa2*qa2 + qa3*qa3;
        float sk = ka0*ka0 + ka1*ka1 + ka2*ka2 + ka3*ka3;
#pragma unroll
        for (int s = 16; s > 0; s >>= 1) {
            sq += __shfl_down_sync(0xffffffffu, sq, s);
            sk += __shfl_down_sync(0xffffffffu, sk, s);
        }
        if ((t & 31) == 0) { red[t >> 5][0] = sq; red[t >> 5][1] = sk; }
        __syncthreads();
        if (t == 0) {
            float s1s = 0.0f, s2s = 0.0f;
#pragma unroll
            for (int w2 = 0; w2 < 8; w2++) { s1s += red[w2][0]; s2s += red[w2][1]; }
            atomicAdd(&g_nq[b*64 + c], s1s);
            atomicAdd(&g_nk[b*64 + c], s2s);
        }
    } else {
        int vc = c - 64;
        const float* in = g_qkv + (size_t)(b*192 + 128 + vc)*NN;
        float wl[9];
#pragma unroll
        for (int q = 0; q < 9; q++) wl[q] = wdw[(128 + vc)*9 + q];
        vhist[t] = 0;
        __syncthreads();
        float a0 = 0.f, a1 = 0.f, a2 = 0.f, a3 = 0.f;
#pragma unroll
        for (int ky = 0; ky < 3; ky++) {
            int ii = i + ky - 1;
            if (ii < 0 || ii > 255) continue;
            const float* row = in + ii*256;
            float4 c4 = *(const float4*)(row + j0);
            float lf = (j0 > 0)   ? row[j0 - 1] : 0.0f;
            float rt = (j0 < 252) ? row[j0 + 4] : 0.0f;
            float w0 = wl[ky*3+0], w1 = wl[ky*3+1], w2 = wl[ky*3+2];
            a0 += w0*lf   + w1*c4.x + w2*c4.y;
            a1 += w0*c4.x + w1*c4.y + w2*c4.z;
            a2 += w0*c4.y + w1*c4.z + w2*c4.w;
            a3 += w0*c4.z + w1*c4.w + w2*rt;
        }
        int seg = b*64 + vc;
        unsigned k0 = fkey(a0), k1 = fkey(a1), k2 = fkey(a2), k3 = fkey(a3);
        uint4 kk; kk.x = k0; kk.y = k1; kk.z = k2; kk.w = k3;
        *(uint4*)(K0 + (size_t)seg*NN + p) = kk;
        atomicAdd(&vhist[(k0 >> 8) & 255u], 1u);
        atomicAdd(&vhist[(k1 >> 8) & 255u], 1u);
        atomicAdd(&vhist[(k2 >> 8) & 255u], 1u);
        atomicAdd(&vhist[(k3 >> 8) & 255u], 1u);
        __syncthreads();
        unsigned v = vhist[t];
        if (v) {
            int blk = blockIdx.y >> 2;
            atomicAdd(&cntA[(seg*16 + blk)*256 + t], v);
        }
    }
}

// K5: per-segment scan of counts -> within-segment offsets
__global__ __launch_bounds__(256) void k_scan(unsigned* __restrict__ cnt) {
    __shared__ unsigned cl[16][256];
    __shared__ unsigned scn[256];
    int seg = blockIdx.x, t = threadIdx.x;
    for (int blk = 0; blk < 16; blk++)
        cl[blk][t] = cnt[(seg*16 + blk)*256 + t];
    __syncthreads();
    unsigned s = 0;
    for (int blk = 0; blk < 16; blk++) s += cl[blk][t];
    unsigned mytot = s;
    scn[t] = s;
    __syncthreads();
    for (int off = 1; off < 256; off <<= 1) {
        unsigned v = scn[t];
        unsigned add = (t >= off) ? scn[t - off] : 0;
        __syncthreads();
        scn[t] = v + add;
        __syncthreads();
    }
    unsigned run = scn[t] - mytot;
    for (int blk = 0; blk < 16; blk++) {
        cnt[(seg*16 + blk)*256 + t] = run;
        run += cl[blk][t];
    }
}

// K6: stable scatter (R9-proven) — split u32 key / u16 pos; dp4a byte-prefix ranking
__global__ __launch_bounds__(256) void k_scatter(const unsigned* __restrict__ srcK,
                                                 const unsigned short* __restrict__ srcP,
                                                 unsigned* __restrict__ dstK,
                                                 unsigned short* __restrict__ dstP,
                                                 int shift,
                                                 const unsigned* __restrict__ cntCur,
                                                 unsigned* __restrict__ cntNext, int nextshift,
                                                 float* __restrict__ vout,
                                                 unsigned short* __restrict__ iout) {
    extern __shared__ char sm[];
    unsigned* stageK        = (unsigned*)sm;                    // 16384
    unsigned short* stageP  = (unsigned short*)(sm + 16384);    // 8192
    unsigned* h2            = (unsigned*)(sm + 24576);          // 16384
    ull* wcnt64             = (ull*)(sm + 40960);               // 2048
    unsigned* scn           = (unsigned*)(sm + 43008);          // 1024
    unsigned* offsC         = (unsigned*)(sm + 44032);          // 1024
    unsigned short* rankOf  = (unsigned short*)(sm + 45056);    // 8192
    unsigned short* runbase = (unsigned short*)(sm + 53248);    // 512
    unsigned short* startLoc= (unsigned short*)(sm + 53760);    // 512

    int t = threadIdx.x;
    int w = t >> 5;
    unsigned ltm = lmask_lt();
    int base = blockIdx.x * 4096;
    int seg = base >> 16;
    bool doNext = (cntNext != nullptr);
    bool isFinal = (vout != nullptr);

    runbase[t] = 0;
    offsC[t] = cntCur[blockIdx.x*256 + t];
    if (doNext)
        for (int m = t; m < 4096; m += 256) h2[m] = 0;

    unsigned key[16];
    unsigned short pos[16];
#pragma unroll
    for (int r = 0; r < 16; r++) key[r] = srcK[base + r*256 + t];
    if (srcP) {
#pragma unroll
        for (int r = 0; r < 16; r++) pos[r] = srcP[base + r*256 + t];
    } else {
#pragma unroll
        for (int r = 0; r < 16; r++) pos[r] = (unsigned short)((base + r*256 + t) & 65535);
    }

    ull wmask = (1ull << (8*w)) - 1ull;
    for (int r = 0; r < 16; r++) {
        wcnt64[t] = 0ull;
        __syncthreads();
        unsigned d = (key[r] >> shift) & 255u;
        unsigned mask = __match_any_sync(0xffffffffu, d);
        unsigned lr = __popc(mask & ltm);
        if (lr == 0)
            ((unsigned char*)&wcnt64[d])[w] = (unsigned char)__popc(mask);
        __syncthreads();
        ull cd = wcnt64[d];
        ull ct = wcnt64[t];
        rankOf[r*256 + t] = (unsigned short)((unsigned)runbase[d] + bytesum(cd & wmask) + lr);
        __syncthreads();
        runbase[t] = (unsigned short)((unsigned)runbase[t] + bytesum(ct));
    }
    __syncthreads();
    unsigned mycnt = runbase[t];
    scn[t] = mycnt;
    __syncthreads();
    for (int off = 1; off < 256; off <<= 1) {
        unsigned v = scn[t];
        unsigned add = (t >= off) ? scn[t - off] : 0;
        __syncthreads();
        scn[t] = v + add;
        __syncthreads();
    }
    startLoc[t] = (unsigned short)(scn[t] - mycnt);
    __syncthreads();
#pragma unroll
    for (int r = 0; r < 16; r++) {
        unsigned d = (key[r] >> shift) & 255u;
        unsigned rank = rankOf[r*256 + t];
        unsigned sl = startLoc[d];
        stageK[sl + rank] = key[r];
        stageP[sl + rank] = pos[r];
        if (doNext) {
            unsigned ds = offsC[d] + rank;
            unsigned d2 = (key[r] >> nextshift) & 255u;
            atomicAdd(&h2[(ds >> 12)*256 + d2], 1u);
        }
    }
    __syncthreads();
    unsigned segbase = (unsigned)seg << 16;
    if (!isFinal) {
#pragma unroll
        for (int r = 0; r < 16; r++) {
            int j = r*256 + t;
            unsigned k2 = stageK[j];
            unsigned d = (k2 >> shift) & 255u;
            unsigned dsti = segbase + offsC[d] + (unsigned)j - startLoc[d];
            dstK[dsti] = k2;
            dstP[dsti] = stageP[j];
        }
    } else {
#pragma unroll
        for (int r = 0; r < 16; r++) {
            int j = r*256 + t;
            unsigned k2 = stageK[j];
            unsigned d = (k2 >> shift) & 255u;
            unsigned dsti = segbase + offsC[d] + (unsigned)j - startLoc[d];
            vout[dsti] = fdec(k2);
            iout[dsti] = stageP[j];
        }
    }
    if (doNext) {
        __syncthreads();
        for (int m = t; m < 4096; m += 256) {
            unsigned v = h2[m];
            if (v) atomicAdd(&cntNext[(seg*16 + (m >> 8))*256 + (m & 255)], v);
        }
    }
}

// K7: raw 8x8 Gram per (b,head) — float2 gather; streaming id reads; smem combine
__global__ __launch_bounds__(256) void k_attn(const unsigned short* __restrict__ iall) {
    __shared__ float wsum[8][64];
    int bh = blockIdx.x; int b = bh >> 3, h = bh & 7;
    const float2* qk = ((const float2*)g_dw) + (size_t)(b*64 + h*8)*NN;
    const unsigned short* ip = iall + (size_t)(b*64 + h*8)*NN;
    float acc[64];
#pragma unroll
    for (int m = 0; m < 64; m++) acc[m] = 0.0f;
    int i0 = blockIdx.y * 4096;
    for (int i = i0 + threadIdx.x; i < i0 + 4096; i += 256) {
        unsigned id[8]; float qv[8], kv[8];
#pragma unroll
        for (int c = 0; c < 8; c++) id[c] = __ldcs(ip + c*NN + i);
#pragma unroll
        for (int c = 0; c < 8; c++) {
            float2 p = qk[(size_t)c*NN + id[c]];
            qv[c] = p.x; kv[c] = p.y;
        }
#pragma unroll
        for (int c = 0; c < 8; c++)
#pragma unroll
            for (int d = 0; d < 8; d++) acc[c*8+d] += qv[c]*kv[d];
    }
#pragma unroll
    for (int m = 0; m < 64; m++) {
#pragma unroll
        for (int s = 16; s > 0; s >>= 1)
            acc[m] += __shfl_down_sync(0xffffffffu, acc[m], s);
    }
    int w = threadIdx.x >> 5;
    if ((threadIdx.x & 31) == 0)
#pragma unroll
        for (int m = 0; m < 64; m++) wsum[w][m] = acc[m];
    __syncthreads();
    if (threadIdx.x < 64) {
        float s = 0.0f;
#pragma unroll
        for (int w2 = 0; w2 < 8; w2++) s += wsum[w2][threadIdx.x];
        atomicAdd(&g_attnraw[bh*64 + threadIdx.x], s);
    }
}

// K8: normalize + temperature + softmax
__global__ __launch_bounds__(512) void k_softmax(const float* __restrict__ temp) {
    int t = threadIdx.x;
    int b = t >> 6, h = (t >> 3) & 7, c = t & 7;
    int bh = b*8 + h;
    float nq = fmaxf(sqrtf(g_nq[b*64 + h*8 + c]), 1e-12f);
    float tp = temp[h];
    float a[8];
    float mx = -FLT_MAX;
#pragma unroll
    for (int d = 0; d < 8; d++) {
        float nk = fmaxf(sqrtf(g_nk[b*64 + h*8 + d]), 1e-12f);
        a[d] = g_attnraw[bh*64 + c*8 + d] / (nq*nk) * tp;
        mx = fmaxf(mx, a[d]);
    }
    float s = 0.0f;
#pragma unroll
    for (int d = 0; d < 8; d++) { a[d] = expf(a[d] - mx); s += a[d]; }
    float inv = 1.0f / s;
#pragma unroll
    for (int d = 0; d < 8; d++) g_attn[bh*64 + c*8 + d] = a[d]*inv;
}

// K9: out = attn @ v_s, scattered back; streaming reads protect L2 for scatter writes
__global__ __launch_bounds__(256) void k_av(const float* __restrict__ vall,
                                            const unsigned short* __restrict__ iall) {
    int bh = blockIdx.y; int b = bh >> 3, h = bh & 7;
    __shared__ float a[64];
    __shared__ float redS[8][8];
    __shared__ unsigned redM[8][8];
    if (threadIdx.x < 64) a[threadIdx.x] = g_attn[bh*64 + threadIdx.x];
    __syncthreads();
    int n = blockIdx.x*256 + threadIdx.x;
    int base = (b*64 + h*8)*NN;
    float v[8]; unsigned id[8];
#pragma unroll
    for (int d = 0; d < 8; d++) {
        v[d] = __ldcs(vall + base + d*NN + n);
        id[d] = __ldcs(iall + base + d*NN + n);
    }
    int w = threadIdx.x >> 5, lane = threadIdx.x & 31;
#pragma unroll
    for (int c = 0; c < 8; c++) {
        float s = 0.0f;
#pragma unroll
        for (int d = 0; d < 8; d++) s += a[c*8+d]*v[d];
        g_out[base + c*NN + id[c]] = s;
        float ssum = s;
        unsigned smax = fkey(s);
#pragma unroll
        for (int sh = 16; sh > 0; sh >>= 1) {
            ssum += __shfl_down_sync(0xffffffffu, ssum, sh);
            smax = max(smax, __shfl_down_sync(0xffffffffu, smax, sh));
        }
        if (lane == 0) { redS[c][w] = ssum; redM[c][w] = smax; }
    }
    __syncthreads();
    if (threadIdx.x < 8) {
        int c = threadIdx.x;
        float s = 0.0f; unsigned m = 0;
#pragma unroll
        for (int w2 = 0; w2 < 8; w2++) { s += redS[c][w2]; m = max(m, redM[c][w2]); }
        atomicAdd(&g_chsum[b*64 + h*8 + c], s);
        atomicMax(&g_chmaxu[b*64 + h*8 + c], m);
    }
}

// K10: channel attention
__global__ __launch_bounds__(64) void k_ca(const float* __restrict__ wfc1, const float* __restrict__ wfc2) {
    int b = blockIdx.x, c = threadIdx.x;
    __shared__ float mv[64], xv[64];
    mv[c] = g_chsum[b*64 + c] * (1.0f/65536.0f);
    xv[c] = fdec(g_chmaxu[b*64 + c]);
    __syncthreads();
    float r1[4], r2[4];
#pragma unroll
    for (int j = 0; j < 4; j++) {
        float s1 = 0.0f, s2 = 0.0f;
        for (int cc = 0; cc < 64; cc++) {
            float w = wfc1[j*64 + cc];
            s1 += mv[cc]*w; s2 += xv[cc]*w;
        }
        r1[j] = s1 * sigm(s1);
        r2[j] = s2 * sigm(s2);
    }
    float t1 = 0.0f, t2 = 0.0f;
#pragma unroll
    for (int j = 0; j < 4; j++) { t1 += r1[j]*wfc2[c*4 + j]; t2 += r2[j]*wfc2[c*4 + j]; }
    g_ca[b*64 + c] = sigm(t1) + sigm(t2);
}

// K11: spatial stats
__global__ __launch_bounds__(256) void k_sp() {
    int b = blockIdx.y;
    int n = blockIdx.x*256 + threadIdx.x;
    __shared__ float cas[64];
    if (threadIdx.x < 64) cas[threadIdx.x] = g_ca[b*64 + threadIdx.x];
    __syncthreads();
    float s = 0.0f, mx = -FLT_MAX, mn = FLT_MAX;
    for (int c = 0; c < 64; c++) {
        float v = g_out[(b*64 + c)*NN + n] * cas[c];
        s += v; mx = fmaxf(mx, v); mn = fminf(mn, v);
    }
    g_sp[(b*4 + 0)*NN + n] = s * (1.0f/64.0f);
    g_sp[(b*4 + 1)*NN + n] = mx;
    g_sp[(b*4 + 2)*NN + n] = mn;
    g_sp[(b*4 + 3)*NN + n] = s;
}

// K12: 7x7 conv (4->1) + silu + 1x1 + sigmoid
__global__ __launch_bounds__(256) void k_sa(const float* __restrict__ wsp1, const float* __restrict__ bsp1,
                                            const float* __restrict__ wsp2, const float* __restrict__ bsp2) {
    __shared__ float tile[4][22][22];
    __shared__ float ws[196];
    int b = blockIdx.z;
    int y0 = blockIdx.y*16, x0 = blockIdx.x*16;
    int tx = threadIdx.x & 15, ty = threadIdx.x >> 4;
    int tid = threadIdx.x;
    if (tid < 196) ws[tid] = wsp1[tid];
    for (int m = tid; m < 4*484; m += 256) {
        int ic = m / 484, rr = m % 484;
        int iy = rr / 22, ix = rr % 22;
        int gy = y0 + iy - 3, gx = x0 + ix - 3;
        tile[ic][iy][ix] = (gy >= 0 && gy < 256 && gx >= 0 && gx < 256)
                           ? g_sp[(b*4 + ic)*NN + gy*256 + gx] : 0.0f;
    }
    __syncthreads();
    float acc = 0.0f;
#pragma unroll
    for (int ic = 0; ic < 4; ic++)
#pragma unroll
        for (int ky = 0; ky < 7; ky++)
#pragma unroll
            for (int kx = 0; kx < 7; kx++)
                acc += ws[ic*49 + ky*7 + kx] * tile[ic][ty+ky][tx+kx];
    float s = acc + bsp1[0];
    float sl = s * sigm(s);
    float t2 = wsp2[0]*sl + bsp2[0];
    g_sa[b*NN + (y0+ty)*256 + x0+tx] = sigm(t2);
}

// K13: projection GEMM + ca*sa scaling + inverse permutations (c<32)
__global__ __launch_bounds__(256) void k_proj(const float* __restrict__ wproj, float* __restrict__ out) {
    __shared__ float xs[64][128];
    __shared__ float wp[64][64];
    __shared__ float sas[128];
    __shared__ float cas[64];
    int b = blockIdx.y;
    int p0 = blockIdx.x * 128, t = threadIdx.x;
    if (t < 64) cas[t] = g_ca[b*64 + t];
    if (t < 128) sas[t] = g_sa[b*NN + p0 + t];
    __syncthreads();
    for (int m = t; m < 64*128; m += 256) {
        int c = m >> 7, px = m & 127;
        xs[c][px] = g_out[(b*64 + c)*NN + p0 + px] * cas[c];
    }
    for (int m = t; m < 4096; m += 256) {
        int o = m >> 6, c = m & 63;
        wp[o][c] = wproj[o*64 + c];
    }
    __syncthreads();
    int ob = (t >> 5) * 8, pb = (t & 31) * 4;
    float acc[8][4];
#pragma unroll
    for (int u = 0; u < 8; u++)
#pragma unroll
        for (int v = 0; v < 4; v++) acc[u][v] = 0.0f;
#pragma unroll 4
    for (int c0 = 0; c0 < 64; c0 += 4) {
        float4 wv[8];
#pragma unroll
        for (int u = 0; u < 8; u++) wv[u] = *(const float4*)&wp[ob + u][c0];
#pragma unroll
        for (int cc = 0; cc < 4; cc++) {
            float4 xv = *(const float4*)&xs[c0 + cc][pb];
#pragma unroll
            for (int u = 0; u < 8; u++) {
                float wu = (cc == 0) ? wv[u].x : (cc == 1) ? wv[u].y : (cc == 2) ? wv[u].z : wv[u].w;
                acc[u][0] += wu*xv.x; acc[u][1] += wu*xv.y;
                acc[u][2] += wu*xv.z; acc[u][3] += wu*xv.w;
            }
        }
    }
#pragma unroll
    for (int u = 0; u < 8; u++) {
        int o = ob + u;
        if (o >= 32) {
#pragma unroll
            for (int v = 0; v < 4; v++)
                out[(b*64 + o)*NN + p0 + pb + v] = acc[u][v] * sas[pb + v];
        } else {
            int ibase = (b*32 + o) * NN;
#pragma unroll
            for (int v = 0; v < 4; v++) {
                int n = p0 + pb + v;
                int q = n >> 8, p = n & 255;
                int j = (int)g_idxw[ibase + q*256 + p];
                int r = (int)g_idxh[ibase + q*256 + j];
                out[(b*64 + o)*NN + r*256 + j] = acc[u][v] * sas[pb + v];
            }
        }
    }
}

extern "C" void kernel_launch(void* const* d_in, const int* in_sizes, int n_in,
                              void* d_out, int out_size) {
    const float* x     = (const float*)d_in[0];
    const float* temp  = (const float*)d_in[1];
    const float* wqkv  = (const float*)d_in[2];
    const float* wdw   = (const float*)d_in[3];
    const float* wfc1  = (const float*)d_in[4];
    const float* wfc2  = (const float*)d_in[5];
    const float* wsp1  = (const float*)d_in[6];
    const float* bsp1  = (const float*)d_in[7];
    const float* wsp2  = (const float*)d_in[8];
    const float* bsp2  = (const float*)d_in[9];
    const float* wproj = (const float*)d_in[10];
    float* out = (float*)d_out;

    cudaFuncSetAttribute(k_scatter, cudaFuncAttributeMaxDynamicSharedMemorySize, 54272);
    cudaFuncSetAttribute(k_qkv, cudaFuncAttributeMaxDynamicSharedMemorySize, 82944);

    void *pS0, *pS1, *pattn, *pnq, *pnk, *pchs, *pchm, *pA, *pB, *pC, *pvx, *pqkv;
    cudaGetSymbolAddress(&pS0, g_keys0);
    cudaGetSymbolAddress(&pS1, g_keys1);
    cudaGetSymbolAddress(&pattn, g_attnraw);
    cudaGetSymbolAddress(&pnq, g_nq);
    cudaGetSymbolAddress(&pnk, g_nk);
    cudaGetSymbolAddress(&pchs, g_chsum);
    cudaGetSymbolAddress(&pchm, g_chmaxu);
    cudaGetSymbolAddress(&pA, g_cntA);
    cudaGetSymbolAddress(&pB, g_cntB);
    cudaGetSymbolAddress(&pC, g_cntC);
    cudaGetSymbolAddress(&pvx, g_x);
    cudaGetSymbolAddress(&pqkv, g_qkv);
    unsigned* K0 = (unsigned*)pS0;
    unsigned short* P0 = (unsigned short*)((unsigned*)pS0 + TOT);
    unsigned* K1 = (unsigned*)pS1;
    unsigned short* P1 = (unsigned short*)((unsigned*)pS1 + TOT);
    unsigned* cntA = (unsigned*)pA;
    unsigned* cntB = (unsigned*)pB;
    unsigned* cntC = (unsigned*)pC;
    float* vall = (float*)pvx;
    unsigned short* iall = (unsigned short*)pqkv;
    const size_t CNT_BYTES = 512ull*16*256*4;

    cudaMemsetAsync(pnq, 0, sizeof(float)*BB*CC);
    cudaMemsetAsync(pnk, 0, sizeof(float)*BB*CC);
    cudaMemsetAsync(pchs, 0, sizeof(float)*BB*CC);
    cudaMemsetAsync(pchm, 0, sizeof(unsigned)*BB*CC);
    cudaMemsetAsync(pattn, 0, sizeof(float)*BB*HEADS*64);
    cudaMemsetAsync(cntA, 0, CNT_BYTES);
    cudaMemsetAsync(cntB, 0, CNT_BYTES);
    cudaMemsetAsync(cntC, 0, CNT_BYTES);

    k_colsort<<<8192, 256>>>(x);
    k_rowsort<<<8192, 256>>>();
    k_qkv<<<dim3(NN/256, BB), 256, 82944>>>(wqkv, x);
    k_dwconv<<<dim3(BB*128, 64), 256>>>(wdw, K0, cntA);

    // segmented radix sort: 3 passes on key bits [8,32)
    k_scan<<<512, 256>>>(cntA);
    k_scatter<<<8192, 256, 54272>>>(K0, nullptr, K1, P1, 8, cntA, cntB, 16, nullptr, nullptr);
    k_scan<<<512, 256>>>(cntB);
    k_scatter<<<8192, 256, 54272>>>(K1, P1, K0, P0, 16, cntB, cntC, 24, nullptr, nullptr);
    k_scan<<<512, 256>>>(cntC);
    k_scatter<<<8192, 256, 54272>>>(K0, P0, nullptr, nullptr, 24, cntC, nullptr, 0, vall, iall);

    k_attn<<<dim3(BB*HEADS, 16), 256>>>(iall);
    k_softmax<<<1, 512>>>(temp);
    k_av<<<dim3(NN/256, BB*HEADS), 256>>>(vall, iall);
    k_ca<<<BB, 64>>>(wfc1, wfc2);
    k_sp<<<dim3(NN/256, BB), 256>>>();
    k_sa<<<dim3(16, 16, BB), 256>>>(wsp1, bsp1, wsp2, bsp2);
    k_proj<<<dim3(NN/128, BB), 256>>>(wproj, out);
}

// round 14
// speedup vs baseline: 1.0328x; 1.0021x over previous
#include <cuda_runtime.h>
#include <math.h>
#include <float.h>

#define BB 8
#define CC 64
#define NN 65536
#define HEADS 8
#define C3 192
#define TOT (BB*CC*NN)
typedef unsigned long long ull;

// ------------------- static scratch -------------------
__device__ __align__(256) float g_x[TOT];                 // sorted x; later v_s floats
__device__ __align__(256) float g_qkv[BB*C3*NN];          // qkv; later id u16 array
__device__ __align__(256) float g_dw[BB*128*NN];          // interleaved (q,k) float2
__device__ __align__(256) ull g_keys0[TOT];               // K0 (u32) + P0 (u16)
__device__ __align__(256) ull g_keys1[TOT];               // K1 + P1
__device__ __align__(256) float g_out[TOT];
__device__ unsigned g_cntA[512*16*256];
__device__ unsigned g_cntB[512*16*256];
__device__ unsigned g_cntC[512*16*256];
__device__ unsigned char g_idxh[BB*32*NN];
__device__ unsigned char g_idxw[BB*32*NN];
__device__ float g_nq[BB*CC], g_nk[BB*CC];
__device__ float g_attnraw[BB*HEADS*64];
__device__ float g_attn[BB*HEADS*64];
__device__ float g_chsum[BB*CC];
__device__ unsigned g_chmaxu[BB*CC];
__device__ float g_ca[BB*CC];
__device__ float g_sp[BB*4*NN];
__device__ float g_sa[BB*NN];

// ------------------- helpers -------------------
__device__ __forceinline__ unsigned fkey(float f) {
    unsigned u = __float_as_uint(f);
    return (u & 0x80000000u) ? ~u : (u | 0x80000000u);
}
__device__ __forceinline__ float fdec(unsigned k) {
    return __uint_as_float((k & 0x80000000u) ? (k ^ 0x80000000u) : ~k);
}
__device__ __forceinline__ float sigm(float x) { return 1.0f / (1.0f + expf(-x)); }
__device__ __forceinline__ unsigned lmask_lt() {
    unsigned m; asm("mov.u32 %0, %%lanemask_lt;" : "=r"(m)); return m;
}
__device__ __forceinline__ unsigned bytesum(ull v) {
    unsigned s = __dp4a((unsigned)v, 0x01010101u, 0u);
    return __dp4a((unsigned)(v >> 32), 0x01010101u, s);
}
// packed fp32x2 FMA (sm_103a)
__device__ __forceinline__ void fma2(ull& d, ull a, ull b) {
    asm("fma.rn.f32x2 %0, %1, %2, %0;" : "+l"(d) : "l"(a), "l"(b));
}
__device__ __forceinline__ ull pk2(float v) {
    ull r; asm("mov.b64 %0, {%1, %1};" : "=l"(r) : "f"(v)); return r;
}
union F4U { float4 f; ulonglong2 u; };

// Warp-level stable bitonic sort of 256 u64 items, 8 per lane.
__device__ __forceinline__ void warp_bitonic_256(ull v[8], int L) {
#pragma unroll
    for (int k = 2; k <= 256; k <<= 1) {
#pragma unroll
        for (int j = 128; j > 0; j >>= 1) {
            if (j >= k) continue;
            if (j >= 32) {
                int jr = j >> 5;
#pragma unroll
                for (int r = 0; r < 8; r++) {
                    if ((r & jr) == 0) {
                        int r2 = r | jr;
                        bool up = ((r & (k >> 5)) == 0);
                        ull a = v[r], b2 = v[r2];
                        if (up ? (a > b2) : (a < b2)) { v[r] = b2; v[r2] = a; }
                    }
                }
            } else {
#pragma unroll
                for (int r = 0; r < 8; r++) {
                    ull o = __shfl_xor_sync(0xffffffffu, v[r], j);
                    int i = r*32 + L;
                    bool up = ((i & k) == 0);
                    bool lower = ((L & j) == 0);
                    ull mn = (v[r] < o) ? v[r] : o;
                    ull mx = (v[r] < o) ? o : v[r];
                    v[r] = (up == lower) ? mn : mx;
                }
            }
        }
    }
}

// K1: stable sort along h for first 32 channels; also zeroes cntB + small accumulators
__global__ __launch_bounds__(256) void k_colsort(const float* __restrict__ x,
                                                 unsigned* __restrict__ cntB) {
    __shared__ float tile[256][9];
    __shared__ unsigned char sidx[256][9];
    int bx = blockIdx.x;
    int t = threadIdx.x;
    cntB[bx*256 + t] = 0;
    if (bx == 0) {
        for (int m = t; m < BB*CC; m += 256) {
            g_nq[m] = 0.0f; g_nk[m] = 0.0f;
            g_chsum[m] = 0.0f; g_chmaxu[m] = 0u;
        }
        for (int m = t; m < BB*HEADS*64; m += 256) g_attnraw[m] = 0.0f;
    }
    int wt = bx & 31, c = (bx >> 5) & 31, b = bx >> 10;
    int w0 = wt * 8;
    const float* src = x + (((b*64 + c)*256 + t)*256 + w0);
    float4 f0 = *(const float4*)src;
    float4 f1 = *(const float4*)(src + 4);
    tile[t][0]=f0.x; tile[t][1]=f0.y; tile[t][2]=f0.z; tile[t][3]=f0.w;
    tile[t][4]=f1.x; tile[t][5]=f1.y; tile[t][6]=f1.z; tile[t][7]=f1.w;
    __syncthreads();
    int w = t >> 5, L = t & 31;
    ull v[8];
#pragma unroll
    for (int r = 0; r < 8; r++) {
        int i = r*32 + L;
        v[r] = ((ull)fkey(tile[i][w]) << 8) | (unsigned)i;
    }
    warp_bitonic_256(v, L);
#pragma unroll
    for (int r = 0; r < 8; r++) {
        int n = r*32 + L;
        tile[n][w] = fdec((unsigned)(v[r] >> 8));
        sidx[n][w] = (unsigned char)(v[r] & 0xFF);
    }
    __syncthreads();
    float* dst = g_x + (((b*64 + c)*256 + t)*256 + w0);
    float4 o0, o1;
    o0.x=tile[t][0]; o0.y=tile[t][1]; o0.z=tile[t][2]; o0.w=tile[t][3];
    o1.x=tile[t][4]; o1.y=tile[t][5]; o1.z=tile[t][6]; o1.w=tile[t][7];
    *(float4*)dst = o0; *(float4*)(dst + 4) = o1;
    ull ib = 0;
#pragma unroll
    for (int q = 0; q < 8; q++) ib |= (ull)sidx[t][q] << (8*q);
    *(ull*)(g_idxh + (((b*32 + c)*256 + t)*256 + w0)) = ib;
}

// K2: stable sort along w; also zeroes cntA + cntC
__global__ __launch_bounds__(256) void k_rowsort(unsigned* __restrict__ cntA,
                                                 unsigned* __restrict__ cntC) {
    int t = threadIdx.x, w = t >> 5, L = t & 31;
    cntA[blockIdx.x*256 + t] = 0;
    cntC[blockIdx.x*256 + t] = 0;
    int rid = blockIdx.x*8 + w;
    int b = rid >> 13, c = (rid >> 8) & 31, hrow = rid & 255;
    float* base = g_x + (((b*64 + c)*256 + hrow)*256);
    ull v[8];
#pragma unroll
    for (int r = 0; r < 8; r++) {
        int i = r*32 + L;
        v[r] = ((ull)fkey(base[i]) << 8) | (unsigned)i;
    }
    warp_bitonic_256(v, L);
    unsigned char* di = g_idxw + ((size_t)((b*32 + c)*256 + hrow))*256;
#pragma unroll
    for (int r = 0; r < 8; r++) {
        int i = r*32 + L;
        base[i] = fdec((unsigned)(v[r] >> 8));
        di[i] = (unsigned char)(v[r] & 0xFF);
    }
}

// K3: qkv 1x1 conv GEMM — f32x2 packed FMA
__global__ __launch_bounds__(256, 2) void k_qkv(const float* __restrict__ wqkv, const float* __restrict__ x) {
    extern __shared__ char sm[];
    float* xs  = (float*)sm;            // [64][256]
    float* wsT = (float*)(sm + 65536);  // [64][68]
    int b = blockIdx.y;
    int p0 = blockIdx.x * 256, t = threadIdx.x;
    for (int m = t; m < 64*64; m += 256) {
        int c = m >> 6, q = m & 63;
        const float* src = (c < 32) ? (g_x + (b*64 + c)*NN + p0) : (x + (b*64 + c)*NN + p0);
        ((float4*)(xs + c*256))[q] = ((const float4*)src)[q];
    }
    int ob = (t >> 5) * 8, pb = (t & 31) * 4;
    for (int oc = 0; oc < 3; oc++) {
        __syncthreads();
        for (int m = t; m < 4096; m += 256)
            wsT[(m & 63)*68 + (m >> 6)] = wqkv[oc*4096 + m];
        __syncthreads();
        ull acc[8][4];
#pragma unroll
        for (int u = 0; u < 8; u++)
#pragma unroll
            for (int v = 0; v < 4; v++) acc[u][v] = 0ull;
#pragma unroll 4
        for (int c = 0; c < 64; c++) {
            F4U xa, xb;
            xa.f = *(const float4*)(xs + c*256 + pb);
            xb.f = *(const float4*)(xs + c*256 + pb + 128);
            float4 w0 = *(const float4*)(wsT + c*68 + ob);
            float4 w1 = *(const float4*)(wsT + c*68 + ob + 4);
#pragma unroll
            for (int u = 0; u < 4; u++) {
                float wu = (u == 0) ? w0.x : (u == 1) ? w0.y : (u == 2) ? w0.z : w0.w;
                ull wp = pk2(wu);
                fma2(acc[u][0], wp, xa.u.x); fma2(acc[u][1], wp, xa.u.y);
                fma2(acc[u][2], wp, xb.u.x); fma2(acc[u][3], wp, xb.u.y);
            }
#pragma unroll
            for (int u = 0; u < 4; u++) {
                float wu = (u == 0) ? w1.x : (u == 1) ? w1.y : (u == 2) ? w1.z : w1.w;
                ull wp = pk2(wu);
                fma2(acc[u+4][0], wp, xa.u.x); fma2(acc[u+4][1], wp, xa.u.y);
                fma2(acc[u+4][2], wp, xb.u.x); fma2(acc[u+4][3], wp, xb.u.y);
            }
        }
#pragma unroll
        for (int u = 0; u < 8; u++) {
            float* dst = g_qkv + ((size_t)(b*192 + oc*64 + ob + u))*NN + p0;
            F4U o0, o1;
            o0.u.x = acc[u][0]; o0.u.y = acc[u][1];
            o1.u.x = acc[u][2]; o1.u.y = acc[u][3];
            *(float4*)(dst + pb) = o0.f;
            *(float4*)(dst + pb + 128) = o1.f;
        }
    }
}

// K4: depthwise 3x3 — type A (c<64): q&k paired; type B: v -> keys + pass-1 hist
__global__ __launch_bounds__(256) void k_dwconv(const float* __restrict__ wdw, unsigned* __restrict__ K0,
                                                unsigned* __restrict__ cntA) {
    __shared__ float red[8][2];
    __shared__ unsigned vhist[256];
    int cx = blockIdx.x;
    int c = cx & 127, b = cx >> 7;
    int t = threadIdx.x;
    int i = blockIdx.y*4 + (t >> 6);
    int j0 = (t & 63) * 4;
    int p = i*256 + j0;

    if (c < 64) {
        const float* inq = g_qkv + (size_t)(b*192 + c)*NN;
        const float* ink = g_qkv + (size_t)(b*192 + 64 + c)*NN;
        float wq[9], wk[9];
#pragma unroll
        for (int q = 0; q < 9; q++) { wq[q] = wdw[c*9 + q]; wk[q] = wdw[(64 + c)*9 + q]; }
        float qa0=0.f,qa1=0.f,qa2=0.f,qa3=0.f, ka0=0.f,ka1=0.f,ka2=0.f,ka3=0.f;
#pragma unroll
        for (int ky = 0; ky < 3; ky++) {
            int ii = i + ky - 1;
            if (ii < 0 || ii > 255) continue;
            const float* rq = inq + ii*256;
            const float* rk = ink + ii*256;
            float4 cq = *(const float4*)(rq + j0);
            float lq = (j0 > 0)   ? rq[j0 - 1] : 0.0f;
            float rqv = (j0 < 252) ? rq[j0 + 4] : 0.0f;
            float w0 = wq[ky*3+0], w1 = wq[ky*3+1], w2 = wq[ky*3+2];
            qa0 += w0*lq   + w1*cq.x + w2*cq.y;
            qa1 += w0*cq.x + w1*cq.y + w2*cq.z;
            qa2 += w0*cq.y + w1*cq.z + w2*cq.w;
            qa3 += w0*cq.z + w1*cq.w + w2*rqv;
            float4 ck = *(const float4*)(rk + j0);
            float lk = (j0 > 0)   ? rk[j0 - 1] : 0.0f;
            float rkv = (j0 < 252) ? rk[j0 + 4] : 0.0f;
            float v0 = wk[ky*3+0], v1 = wk[ky*3+1], v2 = wk[ky*3+2];
            ka0 += v0*lk   + v1*ck.x + v2*ck.y;
            ka1 += v0*ck.x + v1*ck.y + v2*ck.z;
            ka2 += v0*ck.y + v1*ck.z + v2*ck.w;
            ka3 += v0*ck.z + v1*ck.w + v2*rkv;
        }
        float2* dst = ((float2*)g_dw) + (size_t)(b*64 + c)*NN + p;
        float4 s0; s0.x = qa0; s0.y = ka0; s0.z = qa1; s0.w = ka1;
        float4 s1; s1.x = qa2; s1.y = ka2; s1.z = qa3; s1.w = ka3;
        *(float4*)dst = s0;
        *(float4*)(dst + 2) = s1;
        float sq = qa0*qa0 + qa1*qa1 + qa2*qa2 + qa3*qa3;
        float sk = ka0*ka0 + ka1*ka1 + ka2*ka2 + ka3*ka3;
#pragma unroll
        for (int s = 16; s > 0; s >>= 1) {
            sq += __shfl_down_sync(0xffffffffu, sq, s);
            sk += __shfl_down_sync(0xffffffffu, sk, s);
        }
        if ((t & 31) == 0) { red[t >> 5][0] = sq; red[t >> 5][1] = sk; }
        __syncthreads();
        if (t == 0) {
            float s1s = 0.0f, s2s = 0.0f;
#pragma unroll
            for (int w2 = 0; w2 < 8; w2++) { s1s += red[w2][0]; s2s += red[w2][1]; }
            atomicAdd(&g_nq[b*64 + c], s1s);
            atomicAdd(&g_nk[b*64 + c], s2s);
        }
    } else {
        int vc = c - 64;
        const float* in = g_qkv + (size_t)(b*192 + 128 + vc)*NN;
        float wl[9];
#pragma unroll
        for (int q = 0; q < 9; q++) wl[q] = wdw[(128 + vc)*9 + q];
        vhist[t] = 0;
        __syncthreads();
        float a0 = 0.f, a1 = 0.f, a2 = 0.f, a3 = 0.f;
#pragma unroll
        for (int ky = 0; ky < 3; ky++) {
            int ii = i + ky - 1;
            if (ii < 0 || ii > 255) continue;
            const float* row = in + ii*256;
            float4 c4 = *(const float4*)(row + j0);
            float lf = (j0 > 0)   ? row[j0 - 1] : 0.0f;
            float rt = (j0 < 252) ? row[j0 + 4] : 0.0f;
            float w0 = wl[ky*3+0], w1 = wl[ky*3+1], w2 = wl[ky*3+2];
            a0 += w0*lf   + w1*c4.x + w2*c4.y;
            a1 += w0*c4.x + w1*c4.y + w2*c4.z;
            a2 += w0*c4.y + w1*c4.z + w2*c4.w;
            a3 += w0*c4.z + w1*c4.w + w2*rt;
        }
        int seg = b*64 + vc;
        unsigned k0 = fkey(a0), k1 = fkey(a1), k2 = fkey(a2), k3 = fkey(a3);
        uint4 kk; kk.x = k0; kk.y = k1; kk.z = k2; kk.w = k3;
        *(uint4*)(K0 + (size_t)seg*NN + p) = kk;
        atomicAdd(&vhist[(k0 >> 8) & 255u], 1u);
        atomicAdd(&vhist[(k1 >> 8) & 255u], 1u);
        atomicAdd(&vhist[(k2 >> 8) & 255u], 1u);
        atomicAdd(&vhist[(k3 >> 8) & 255u], 1u);
        __syncthreads();
        unsigned v = vhist[t];
        if (v) {
            int blk = blockIdx.y >> 2;
            atomicAdd(&cntA[(seg*16 + blk)*256 + t], v);
        }
    }
}

// K5: per-segment scan of counts -> within-segment offsets
__global__ __launch_bounds__(256) void k_scan(unsigned* __restrict__ cnt) {
    __shared__ unsigned cl[16][256];
    __shared__ unsigned scn[256];
    int seg = blockIdx.x, t = threadIdx.x;
    for (int blk = 0; blk < 16; blk++)
        cl[blk][t] = cnt[(seg*16 + blk)*256 + t];
    __syncthreads();
    unsigned s = 0;
    for (int blk = 0; blk < 16; blk++) s += cl[blk][t];
    unsigned mytot = s;
    scn[t] = s;
    __syncthreads();
    for (int off = 1; off < 256; off <<= 1) {
        unsigned v = scn[t];
        unsigned add = (t >= off) ? scn[t - off] : 0;
        __syncthreads();
        scn[t] = v + add;
        __syncthreads();
    }
    unsigned run = scn[t] - mytot;
    for (int blk = 0; blk < 16; blk++) {
        cnt[(seg*16 + blk)*256 + t] = run;
        run += cl[blk][t];
    }
}

// K6: stable scatter (R9-proven) — split u32 key / u16 pos; dp4a byte-prefix ranking
__global__ __launch_bounds__(256) void k_scatter(const unsigned* __restrict__ srcK,
                                                 const unsigned short* __restrict__ srcP,
                                                 unsigned* __restrict__ dstK,
                                                 unsigned short* __restrict__ dstP,
                                                 int shift,
                                                 const unsigned* __restrict__ cntCur,
                                                 unsigned* __restrict__ cntNext, int nextshift,
                                                 float* __restrict__ vout,
                                                 unsigned short* __restrict__ iout) {
    extern __shared__ char sm[];
    unsigned* stageK        = (unsigned*)sm;                    // 16384
    unsigned short* stageP  = (unsigned short*)(sm + 16384);    // 8192
    unsigned* h2            = (unsigned*)(sm + 24576);          // 16384
    ull* wcnt64             = (ull*)(sm + 40960);               // 2048
    unsigned* scn           = (unsigned*)(sm + 43008);          // 1024
    unsigned* offsC         = (unsigned*)(sm + 44032);          // 1024
    unsigned short* rankOf  = (unsigned short*)(sm + 45056);    // 8192
    unsigned short* runbase = (unsigned short*)(sm + 53248);    // 512
    unsigned short* startLoc= (unsigned short*)(sm + 53760);    // 512

    int t = threadIdx.x;
    int w = t >> 5;
    unsigned ltm = lmask_lt();
    int base = blockIdx.x * 4096;
    int seg = base >> 16;
    bool doNext = (cntNext != nullptr);
    bool isFinal = (vout != nullptr);

    runbase[t] = 0;
    offsC[t] = cntCur[blockIdx.x*256 + t];
    if (doNext)
        for (int m = t; m < 4096; m += 256) h2[m] = 0;

    unsigned key[16];
    unsigned short pos[16];
#pragma unroll
    for (int r = 0; r < 16; r++) key[r] = srcK[base + r*256 + t];
    if (srcP) {
#pragma unroll
        for (int r = 0; r < 16; r++) pos[r] = srcP[base + r*256 + t];
    } else {
#pragma unroll
        for (int r = 0; r < 16; r++) pos[r] = (unsigned short)((base + r*256 + t) & 65535);
    }

    ull wmask = (1ull << (8*w)) - 1ull;
    for (int r = 0; r < 16; r++) {
        wcnt64[t] = 0ull;
        __syncthreads();
        unsigned d = (key[r] >> shift) & 255u;
        unsigned mask = __match_any_sync(0xffffffffu, d);
        unsigned lr = __popc(mask & ltm);
        if (lr == 0)
            ((unsigned char*)&wcnt64[d])[w] = (unsigned char)__popc(mask);
        __syncthreads();
        ull cd = wcnt64[d];
        ull ct = wcnt64[t];
        rankOf[r*256 + t] = (unsigned short)((unsigned)runbase[d] + bytesum(cd & wmask) + lr);
        __syncthreads();
        runbase[t] = (unsigned short)((unsigned)runbase[t] + bytesum(ct));
    }
    __syncthreads();
    unsigned mycnt = runbase[t];
    scn[t] = mycnt;
    __syncthreads();
    for (int off = 1; off < 256; off <<= 1) {
        unsigned v = scn[t];
        unsigned add = (t >= off) ? scn[t - off] : 0;
        __syncthreads();
        scn[t] = v + add;
        __syncthreads();
    }
    startLoc[t] = (unsigned short)(scn[t] - mycnt);
    __syncthreads();
#pragma unroll
    for (int r = 0; r < 16; r++) {
        unsigned d = (key[r] >> shift) & 255u;
        unsigned rank = rankOf[r*256 + t];
        unsigned sl = startLoc[d];
        stageK[sl + rank] = key[r];
        stageP[sl + rank] = pos[r];
        if (doNext) {
            unsigned ds = offsC[d] + rank;
            unsigned d2 = (key[r] >> nextshift) & 255u;
            atomicAdd(&h2[(ds >> 12)*256 + d2], 1u);
        }
    }
    __syncthreads();
    unsigned segbase = (unsigned)seg << 16;
    if (!isFinal) {
#pragma unroll
        for (int r = 0; r < 16; r++) {
            int j = r*256 + t;
            unsigned k2 = stageK[j];
            unsigned d = (k2 >> shift) & 255u;
            unsigned dsti = segbase + offsC[d] + (unsigned)j - startLoc[d];
            dstK[dsti] = k2;
            dstP[dsti] = stageP[j];
        }
    } else {
#pragma unroll
        for (int r = 0; r < 16; r++) {
            int j = r*256 + t;
            unsigned k2 = stageK[j];
            unsigned d = (k2 >> shift) & 255u;
            unsigned dsti = segbase + offsC[d] + (unsigned)j - startLoc[d];
            vout[dsti] = fdec(k2);
            iout[dsti] = stageP[j];
        }
    }
    if (doNext) {
        __syncthreads();
        for (int m = t; m < 4096; m += 256) {
            unsigned v = h2[m];
            if (v) atomicAdd(&cntNext[(seg*16 + (m >> 8))*256 + (m & 255)], v);
        }
    }
}

// K7: raw 8x8 Gram per (b,head) — float2 gather; streaming id reads; smem combine
__global__ __launch_bounds__(256) void k_attn(const unsigned short* __restrict__ iall) {
    __shared__ float wsum[8][64];
    int bh = blockIdx.x; int b = bh >> 3, h = bh & 7;
    const float2* qk = ((const float2*)g_dw) + (size_t)(b*64 + h*8)*NN;
    const unsigned short* ip = iall + (size_t)(b*64 + h*8)*NN;
    float acc[64];
#pragma unroll
    for (int m = 0; m < 64; m++) acc[m] = 0.0f;
    int i0 = blockIdx.y * 4096;
    for (int i = i0 + threadIdx.x; i < i0 + 4096; i += 256) {
        unsigned id[8]; float qv[8], kv[8];
#pragma unroll
        for (int c = 0; c < 8; c++) id[c] = __ldcs(ip + c*NN + i);
#pragma unroll
        for (int c = 0; c < 8; c++) {
            float2 p = qk[(size_t)c*NN + id[c]];
            qv[c] = p.x; kv[c] = p.y;
        }
#pragma unroll
        for (int c = 0; c < 8; c++)
#pragma unroll
            for (int d = 0; d < 8; d++) acc[c*8+d] += qv[c]*kv[d];
    }
#pragma unroll
    for (int m = 0; m < 64; m++) {
#pragma unroll
        for (int s = 16; s > 0; s >>= 1)
            acc[m] += __shfl_down_sync(0xffffffffu, acc[m], s);
    }
    int w = threadIdx.x >> 5;
    if ((threadIdx.x & 31) == 0)
#pragma unroll
        for (int m = 0; m < 64; m++) wsum[w][m] = acc[m];
    __syncthreads();
    if (threadIdx.x < 64) {
        float s = 0.0f;
#pragma unroll
        for (int w2 = 0; w2 < 8; w2++) s += wsum[w2][threadIdx.x];
        atomicAdd(&g_attnraw[bh*64 + threadIdx.x], s);
    }
}

// K8: normalize + temperature + softmax
__global__ __launch_bounds__(512) void k_softmax(const float* __restrict__ temp) {
    int t = threadIdx.x;
    int b = t >> 6, h = (t >> 3) & 7, c = t & 7;
    int bh = b*8 + h;
    float nq = fmaxf(sqrtf(g_nq[b*64 + h*8 + c]), 1e-12f);
    float tp = temp[h];
    float a[8];
    float mx = -FLT_MAX;
#pragma unroll
    for (int d = 0; d < 8; d++) {
        float nk = fmaxf(sqrtf(g_nk[b*64 + h*8 + d]), 1e-12f);
        a[d] = g_attnraw[bh*64 + c*8 + d] / (nq*nk) * tp;
        mx = fmaxf(mx, a[d]);
    }
    float s = 0.0f;
#pragma unroll
    for (int d = 0; d < 8; d++) { a[d] = expf(a[d] - mx); s += a[d]; }
    float inv = 1.0f / s;
#pragma unroll
    for (int d = 0; d < 8; d++) g_attn[bh*64 + c*8 + d] = a[d]*inv;
}

// K9: out = attn @ v_s, scattered back; fused per-channel sum/max
__global__ __launch_bounds__(256) void k_av(const float* __restrict__ vall,
                                            const unsigned short* __restrict__ iall) {
    int bh = blockIdx.y; int b = bh >> 3, h = bh & 7;
    __shared__ float a[64];
    __shared__ float redS[8][8];
    __shared__ unsigned redM[8][8];
    if (threadIdx.x < 64) a[threadIdx.x] = g_attn[bh*64 + threadIdx.x];
    __syncthreads();
    int n = blockIdx.x*256 + threadIdx.x;
    int base = (b*64 + h*8)*NN;
    float v[8]; unsigned id[8];
#pragma unroll
    for (int d = 0; d < 8; d++) {
        v[d] = __ldcs(vall + base + d*NN + n);
        id[d] = __ldcs(iall + base + d*NN + n);
    }
    int w = threadIdx.x >> 5, lane = threadIdx.x & 31;
#pragma unroll
    for (int c = 0; c < 8; c++) {
        float s = 0.0f;
#pragma unroll
        for (int d = 0; d < 8; d++) s += a[c*8+d]*v[d];
        g_out[base + c*NN + id[c]] = s;
        float ssum = s;
        unsigned smax = fkey(s);
#pragma unroll
        for (int sh = 16; sh > 0; sh >>= 1) {
            ssum += __shfl_down_sync(0xffffffffu, ssum, sh);
            smax = max(smax, __shfl_down_sync(0xffffffffu, smax, sh));
        }
        if (lane == 0) { redS[c][w] = ssum; redM[c][w] = smax; }
    }
    __syncthreads();
    if (threadIdx.x < 8) {
        int c = threadIdx.x;
        float s = 0.0f; unsigned m = 0;
#pragma unroll
        for (int w2 = 0; w2 < 8; w2++) { s += redS[c][w2]; m = max(m, redM[c][w2]); }
        atomicAdd(&g_chsum[b*64 + h*8 + c], s);
        atomicMax(&g_chmaxu[b*64 + h*8 + c], m);
    }
}

// K10: channel attention
__global__ __launch_bounds__(64) void k_ca(const float* __restrict__ wfc1, const float* __restrict__ wfc2) {
    int b = blockIdx.x, c = threadIdx.x;
    __shared__ float mv[64], xv[64];
    mv[c] = g_chsum[b*64 + c] * (1.0f/65536.0f);
    xv[c] = fdec(g_chmaxu[b*64 + c]);
    __syncthreads();
    float r1[4], r2[4];
#pragma unroll
    for (int j = 0; j < 4; j++) {
        float s1 = 0.0f, s2 = 0.0f;
        for (int cc = 0; cc < 64; cc++) {
            float w = wfc1[j*64 + cc];
            s1 += mv[cc]*w; s2 += xv[cc]*w;
        }
        r1[j] = s1 * sigm(s1);
        r2[j] = s2 * sigm(s2);
    }
    float t1 = 0.0f, t2 = 0.0f;
#pragma unroll
    for (int j = 0; j < 4; j++) { t1 += r1[j]*wfc2[c*4 + j]; t2 += r2[j]*wfc2[c*4 + j]; }
    g_ca[b*64 + c] = sigm(t1) + sigm(t2);
}

// K11: spatial stats
__global__ __launch_bounds__(256) void k_sp() {
    int b = blockIdx.y;
    int n = blockIdx.x*256 + threadIdx.x;
    __shared__ float cas[64];
    if (threadIdx.x < 64) cas[threadIdx.x] = g_ca[b*64 + threadIdx.x];
    __syncthreads();
    float s = 0.0f, mx = -FLT_MAX, mn = FLT_MAX;
    for (int c = 0; c < 64; c++) {
        float v = g_out[(b*64 + c)*NN + n] * cas[c];
        s += v; mx = fmaxf(mx, v); mn = fminf(mn, v);
    }
    g_sp[(b*4 + 0)*NN + n] = s * (1.0f/64.0f);
    g_sp[(b*4 + 1)*NN + n] = mx;
    g_sp[(b*4 + 2)*NN + n] = mn;
    g_sp[(b*4 + 3)*NN + n] = s;
}

// K12: 7x7 conv (4->1) + silu + 1x1 + sigmoid
__global__ __launch_bounds__(256) void k_sa(const float* __restrict__ wsp1, const float* __restrict__ bsp1,
                                            const float* __restrict__ wsp2, const float* __restrict__ bsp2) {
    __shared__ float tile[4][22][22];
    __shared__ float ws[196];
    int b = blockIdx.z;
    int y0 = blockIdx.y*16, x0 = blockIdx.x*16;
    int tx = threadIdx.x & 15, ty = threadIdx.x >> 4;
    int tid = threadIdx.x;
    if (tid < 196) ws[tid] = wsp1[tid];
    for (int m = tid; m < 4*484; m += 256) {
        int ic = m / 484, rr = m % 484;
        int iy = rr / 22, ix = rr % 22;
        int gy = y0 + iy - 3, gx = x0 + ix - 3;
        tile[ic][iy][ix] = (gy >= 0 && gy < 256 && gx >= 0 && gx < 256)
                           ? g_sp[(b*4 + ic)*NN + gy*256 + gx] : 0.0f;
    }
    __syncthreads();
    float acc = 0.0f;
#pragma unroll
    for (int ic = 0; ic < 4; ic++)
#pragma unroll
        for (int ky = 0; ky < 7; ky++)
#pragma unroll
            for (int kx = 0; kx < 7; kx++)
                acc += ws[ic*49 + ky*7 + kx] * tile[ic][ty+ky][tx+kx];
    float s = acc + bsp1[0];
    float sl = s * sigm(s);
    float t2 = wsp2[0]*sl + bsp2[0];
    g_sa[b*NN + (y0+ty)*256 + x0+tx] = sigm(t2);
}

// K13: projection GEMM + ca*sa scaling + inverse permutations (c<32)
__global__ __launch_bounds__(256) void k_proj(const float* __restrict__ wproj, float* __restrict__ out) {
    __shared__ float xs[64][128];
    __shared__ float wp[64][64];
    __shared__ float sas[128];
    __shared__ float cas[64];
    int b = blockIdx.y;
    int p0 = blockIdx.x * 128, t = threadIdx.x;
    if (t < 64) cas[t] = g_ca[b*64 + t];
    if (t < 128) sas[t] = g_sa[b*NN + p0 + t];
    __syncthreads();
    for (int m = t; m < 64*128; m += 256) {
        int c = m >> 7, px = m & 127;
        xs[c][px] = g_out[(b*64 + c)*NN + p0 + px] * cas[c];
    }
    for (int m = t; m < 4096; m += 256) {
        int o = m >> 6, c = m & 63;
        wp[o][c] = wproj[o*64 + c];
    }
    __syncthreads();
    int ob = (t >> 5) * 8, pb = (t & 31) * 4;
    float acc[8][4];
#pragma unroll
    for (int u = 0; u < 8; u++)
#pragma unroll
        for (int v = 0; v < 4; v++) acc[u][v] = 0.0f;
#pragma unroll 4
    for (int c0 = 0; c0 < 64; c0 += 4) {
        float4 wv[8];
#pragma unroll
        for (int u = 0; u < 8; u++) wv[u] = *(const float4*)&wp[ob + u][c0];
#pragma unroll
        for (int cc = 0; cc < 4; cc++) {
            float4 xv = *(const float4*)&xs[c0 + cc][pb];
#pragma unroll
            for (int u = 0; u < 8; u++) {
                float wu = (cc == 0) ? wv[u].x : (cc == 1) ? wv[u].y : (cc == 2) ? wv[u].z : wv[u].w;
                acc[u][0] += wu*xv.x; acc[u][1] += wu*xv.y;
                acc[u][2] += wu*xv.z; acc[u][3] += wu*xv.w;
            }
        }
    }
#pragma unroll
    for (int u = 0; u < 8; u++) {
        int o = ob + u;
        if (o >= 32) {
#pragma unroll
            for (int v = 0; v < 4; v++)
                out[(b*64 + o)*NN + p0 + pb + v] = acc[u][v] * sas[pb + v];
        } else {
            int ibase = (b*32 + o) * NN;
#pragma unroll
            for (int v = 0; v < 4; v++) {
                int n = p0 + pb + v;
                int q = n >> 8, p = n & 255;
                int j = (int)g_idxw[ibase + q*256 + p];
                int r = (int)g_idxh[ibase + q*256 + j];
                out[(b*64 + o)*NN + r*256 + j] = acc[u][v] * sas[pb + v];
            }
        }
    }
}

extern "C" void kernel_launch(void* const* d_in, const int* in_sizes, int n_in,
                              void* d_out, int out_size) {
    const float* x     = (const float*)d_in[0];
    const float* temp  = (const float*)d_in[1];
    const float* wqkv  = (const float*)d_in[2];
    const float* wdw   = (const float*)d_in[3];
    const float* wfc1  = (const float*)d_in[4];
    const float* wfc2  = (const float*)d_in[5];
    const float* wsp1  = (const float*)d_in[6];
    const float* bsp1  = (const float*)d_in[7];
    const float* wsp2  = (const float*)d_in[8];
    const float* bsp2  = (const float*)d_in[9];
    const float* wproj = (const float*)d_in[10];
    float* out = (float*)d_out;

    cudaFuncSetAttribute(k_scatter, cudaFuncAttributeMaxDynamicSharedMemorySize, 54272);
    cudaFuncSetAttribute(k_qkv, cudaFuncAttributeMaxDynamicSharedMemorySize, 82944);

    void *pS0, *pS1, *pA, *pB, *pC, *pvx, *pqkv;
    cudaGetSymbolAddress(&pS0, g_keys0);
    cudaGetSymbolAddress(&pS1, g_keys1);
    cudaGetSymbolAddress(&pA, g_cntA);
    cudaGetSymbolAddress(&pB, g_cntB);
    cudaGetSymbolAddress(&pC, g_cntC);
    cudaGetSymbolAddress(&pvx, g_x);
    cudaGetSymbolAddress(&pqkv, g_qkv);
    unsigned* K0 = (unsigned*)pS0;
    unsigned short* P0 = (unsigned short*)((unsigned*)pS0 + TOT);
    unsigned* K1 = (unsigned*)pS1;
    unsigned short* P1 = (unsigned short*)((unsigned*)pS1 + TOT);
    unsigned* cntA = (unsigned*)pA;
    unsigned* cntB = (unsigned*)pB;
    unsigned* cntC = (unsigned*)pC;
    float* vall = (float*)pvx;
    unsigned short* iall = (unsigned short*)pqkv;

    // all zeroing folded into k_colsort / k_rowsort (run before any consumer)
    k_colsort<<<8192, 256>>>(x, cntB);
    k_rowsort<<<8192, 256>>>(cntA, cntC);
    k_qkv<<<dim3(NN/256, BB), 256, 82944>>>(wqkv, x);
    k_dwconv<<<dim3(BB*128, 64), 256>>>(wdw, K0, cntA);

    // segmented radix sort: 3 passes on key bits [8,32)
    k_scan<<<512, 256>>>(cntA);
    k_scatter<<<8192, 256, 54272>>>(K0, nullptr, K1, P1, 8, cntA, cntB, 16, nullptr, nullptr);
    k_scan<<<512, 256>>>(cntB);
    k_scatter<<<8192, 256, 54272>>>(K1, P1, K0, P0, 16, cntB, cntC, 24, nullptr, nullptr);
    k_scan<<<512, 256>>>(cntC);
    k_scatter<<<8192, 256, 54272>>>(K0, P0, nullptr, nullptr, 24, cntC, nullptr, 0, vall, iall);

    k_attn<<<dim3(BB*HEADS, 16), 256>>>(iall);
    k_softmax<<<1, 512>>>(temp);
    k_av<<<dim3(NN/256, BB*HEADS), 256>>>(vall, iall);
    k_ca<<<BB, 64>>>(wfc1, wfc2);
    k_sp<<<dim3(NN/256, BB), 256>>>();
    k_sa<<<dim3(16, 16, BB), 256>>>(wsp1, bsp1, wsp2, bsp2);
    k_proj<<<dim3(NN/128, BB), 256>>>(wproj, out);
}

// round 15
// speedup vs baseline: 1.0471x; 1.0139x over previous
#include <cuda_runtime.h>
#include <math.h>
#include <float.h>

#define BB 8
#define CC 64
#define NN 65536
#define HEADS 8
#define C3 192
#define TOT (BB*CC*NN)
typedef unsigned long long ull;

// ------------------- static scratch -------------------
__device__ __align__(256) float g_x[TOT];
__device__ __align__(256) float g_qkv[BB*C3*NN];
__device__ __align__(256) float g_dw[BB*128*NN];
__device__ __align__(256) ull g_keys0[TOT];
__device__ __align__(256) ull g_keys1[TOT];
__device__ __align__(256) float g_out[TOT];
__device__ unsigned g_cntA[512*16*256];
__device__ unsigned g_cntB[512*16*256];
__device__ unsigned g_cntC[512*16*256];
__device__ unsigned char g_idxh[BB*32*NN];
__device__ unsigned char g_idxw[BB*32*NN];
__device__ float g_nq[BB*CC], g_nk[BB*CC];
__device__ float g_attnraw[BB*HEADS*64];
__device__ float g_attn[BB*HEADS*64];
__device__ float g_chsum[BB*CC];
__device__ unsigned g_chmaxu[BB*CC];
__device__ float g_ca[BB*CC];
__device__ float g_sp[BB*4*NN];
__device__ float g_sa[BB*NN];

// ------------------- helpers -------------------
__device__ __forceinline__ unsigned fkey(float f) {
    unsigned u = __float_as_uint(f);
    return (u & 0x80000000u) ? ~u : (u | 0x80000000u);
}
__device__ __forceinline__ float fdec(unsigned k) {
    return __uint_as_float((k & 0x80000000u) ? (k ^ 0x80000000u) : ~k);
}
__device__ __forceinline__ float sigm(float x) { return 1.0f / (1.0f + expf(-x)); }
__device__ __forceinline__ unsigned lmask_lt() {
    unsigned m; asm("mov.u32 %0, %%lanemask_lt;" : "=r"(m)); return m;
}
__device__ __forceinline__ unsigned bytesum(ull v) {
    unsigned s = __dp4a((unsigned)v, 0x01010101u, 0u);
    return __dp4a((unsigned)(v >> 32), 0x01010101u, s);
}
__device__ __forceinline__ void fma2(ull& d, ull a, ull b) {
    asm("fma.rn.f32x2 %0, %1, %2, %0;" : "+l"(d) : "l"(a), "l"(b));
}
__device__ __forceinline__ ull pk2(float v) {
    ull r; asm("mov.b64 %0, {%1, %1};" : "=l"(r) : "f"(v)); return r;
}
union F4U { float4 f; ulonglong2 u; };

// Warp-level stable bitonic sort of 256 u64 items, 8 per lane.
__device__ __forceinline__ void warp_bitonic_256(ull v[8], int L) {
#pragma unroll
    for (int k = 2; k <= 256; k <<= 1) {
#pragma unroll
        for (int j = 128; j > 0; j >>= 1) {
            if (j >= k) continue;
            if (j >= 32) {
                int jr = j >> 5;
#pragma unroll
                for (int r = 0; r < 8; r++) {
                    if ((r & jr) == 0) {
                        int r2 = r | jr;
                        bool up = ((r & (k >> 5)) == 0);
                        ull a = v[r], b2 = v[r2];
                        if (up ? (a > b2) : (a < b2)) { v[r] = b2; v[r2] = a; }
                    }
                }
            } else {
#pragma unroll
                for (int r = 0; r < 8; r++) {
                    ull o = __shfl_xor_sync(0xffffffffu, v[r], j);
                    int i = r*32 + L;
                    bool up = ((i & k) == 0);
                    bool lower = ((L & j) == 0);
                    ull mn = (v[r] < o) ? v[r] : o;
                    ull mx = (v[r] < o) ? o : v[r];
                    v[r] = (up == lower) ? mn : mx;
                }
            }
        }
    }
}

// K1: stable sort along h for first 32 channels; also zeroes cntB + small accumulators
__global__ __launch_bounds__(256) void k_colsort(const float* __restrict__ x,
                                                 unsigned* __restrict__ cntB) {
    __shared__ float tile[256][9];
    __shared__ unsigned char sidx[256][9];
    int bx = blockIdx.x;
    int t = threadIdx.x;
    cntB[bx*256 + t] = 0;
    if (bx == 0) {
        for (int m = t; m < BB*CC; m += 256) {
            g_nq[m] = 0.0f; g_nk[m] = 0.0f;
            g_chsum[m] = 0.0f; g_chmaxu[m] = 0u;
        }
        for (int m = t; m < BB*HEADS*64; m += 256) g_attnraw[m] = 0.0f;
    }
    int wt = bx & 31, c = (bx >> 5) & 31, b = bx >> 10;
    int w0 = wt * 8;
    const float* src = x + (((b*64 + c)*256 + t)*256 + w0);
    float4 f0 = *(const float4*)src;
    float4 f1 = *(const float4*)(src + 4);
    tile[t][0]=f0.x; tile[t][1]=f0.y; tile[t][2]=f0.z; tile[t][3]=f0.w;
    tile[t][4]=f1.x; tile[t][5]=f1.y; tile[t][6]=f1.z; tile[t][7]=f1.w;
    __syncthreads();
    int w = t >> 5, L = t & 31;
    ull v[8];
#pragma unroll
    for (int r = 0; r < 8; r++) {
        int i = r*32 + L;
        v[r] = ((ull)fkey(tile[i][w]) << 8) | (unsigned)i;
    }
    warp_bitonic_256(v, L);
#pragma unroll
    for (int r = 0; r < 8; r++) {
        int n = r*32 + L;
        tile[n][w] = fdec((unsigned)(v[r] >> 8));
        sidx[n][w] = (unsigned char)(v[r] & 0xFF);
    }
    __syncthreads();
    float* dst = g_x + (((b*64 + c)*256 + t)*256 + w0);
    float4 o0, o1;
    o0.x=tile[t][0]; o0.y=tile[t][1]; o0.z=tile[t][2]; o0.w=tile[t][3];
    o1.x=tile[t][4]; o1.y=tile[t][5]; o1.z=tile[t][6]; o1.w=tile[t][7];
    *(float4*)dst = o0; *(float4*)(dst + 4) = o1;
    ull ib = 0;
#pragma unroll
    for (int q = 0; q < 8; q++) ib |= (ull)sidx[t][q] << (8*q);
    *(ull*)(g_idxh + (((b*32 + c)*256 + t)*256 + w0)) = ib;
}

// K2: stable sort along w; also zeroes cntA + cntC
__global__ __launch_bounds__(256) void k_rowsort(unsigned* __restrict__ cntA,
                                                 unsigned* __restrict__ cntC) {
    int t = threadIdx.x, w = t >> 5, L = t & 31;
    cntA[blockIdx.x*256 + t] = 0;
    cntC[blockIdx.x*256 + t] = 0;
    int rid = blockIdx.x*8 + w;
    int b = rid >> 13, c = (rid >> 8) & 31, hrow = rid & 255;
    float* base = g_x + (((b*64 + c)*256 + hrow)*256);
    ull v[8];
#pragma unroll
    for (int r = 0; r < 8; r++) {
        int i = r*32 + L;
        v[r] = ((ull)fkey(base[i]) << 8) | (unsigned)i;
    }
    warp_bitonic_256(v, L);
    unsigned char* di = g_idxw + ((size_t)((b*32 + c)*256 + hrow))*256;
#pragma unroll
    for (int r = 0; r < 8; r++) {
        int i = r*32 + L;
        base[i] = fdec((unsigned)(v[r] >> 8));
        di[i] = (unsigned char)(v[r] & 0xFF);
    }
}

// K3: qkv 1x1 conv GEMM — f32x2 packed FMA
__global__ __launch_bounds__(256, 2) void k_qkv(const float* __restrict__ wqkv, const float* __restrict__ x) {
    extern __shared__ char sm[];
    float* xs  = (float*)sm;            // [64][256]
    float* wsT = (float*)(sm + 65536);  // [64][68]
    int b = blockIdx.y;
    int p0 = blockIdx.x * 256, t = threadIdx.x;
    for (int m = t; m < 64*64; m += 256) {
        int c = m >> 6, q = m & 63;
        const float* src = (c < 32) ? (g_x + (b*64 + c)*NN + p0) : (x + (b*64 + c)*NN + p0);
        ((float4*)(xs + c*256))[q] = ((const float4*)src)[q];
    }
    int ob = (t >> 5) * 8, pb = (t & 31) * 4;
    for (int oc = 0; oc < 3; oc++) {
        __syncthreads();
        for (int m = t; m < 4096; m += 256)
            wsT[(m & 63)*68 + (m >> 6)] = wqkv[oc*4096 + m];
        __syncthreads();
        ull acc[8][4];
#pragma unroll
        for (int u = 0; u < 8; u++)
#pragma unroll
            for (int v = 0; v < 4; v++) acc[u][v] = 0ull;
#pragma unroll 4
        for (int c = 0; c < 64; c++) {
            F4U xa, xb;
            xa.f = *(const float4*)(xs + c*256 + pb);
            xb.f = *(const float4*)(xs + c*256 + pb + 128);
            float4 w0 = *(const float4*)(wsT + c*68 + ob);
            float4 w1 = *(const float4*)(wsT + c*68 + ob + 4);
#pragma unroll
            for (int u = 0; u < 4; u++) {
                float wu = (u == 0) ? w0.x : (u == 1) ? w0.y : (u == 2) ? w0.z : w0.w;
                ull wp = pk2(wu);
                fma2(acc[u][0], wp, xa.u.x); fma2(acc[u][1], wp, xa.u.y);
                fma2(acc[u][2], wp, xb.u.x); fma2(acc[u][3], wp, xb.u.y);
            }
#pragma unroll
            for (int u = 0; u < 4; u++) {
                float wu = (u == 0) ? w1.x : (u == 1) ? w1.y : (u == 2) ? w1.z : w1.w;
                ull wp = pk2(wu);
                fma2(acc[u+4][0], wp, xa.u.x); fma2(acc[u+4][1], wp, xa.u.y);
                fma2(acc[u+4][2], wp, xb.u.x); fma2(acc[u+4][3], wp, xb.u.y);
            }
        }
#pragma unroll
        for (int u = 0; u < 8; u++) {
            float* dst = g_qkv + ((size_t)(b*192 + oc*64 + ob + u))*NN + p0;
            F4U o0, o1;
            o0.u.x = acc[u][0]; o0.u.y = acc[u][1];
            o1.u.x = acc[u][2]; o1.u.y = acc[u][3];
            *(float4*)(dst + pb) = o0.f;
            *(float4*)(dst + pb + 128) = o1.f;
        }
    }
}

// K4: depthwise 3x3 v3 — 8 px/thread (warp per row, 8 rows/block)
__global__ __launch_bounds__(256) void k_dwconv(const float* __restrict__ wdw, unsigned* __restrict__ K0,
                                                unsigned* __restrict__ cntA) {
    __shared__ float red[8][2];
    __shared__ unsigned vhist[256];
    int cx = blockIdx.x;
    int c = cx & 127, b = cx >> 7;
    int t = threadIdx.x;
    int i = blockIdx.y*8 + (t >> 5);
    int j0 = (t & 31) * 8;
    int p = i*256 + j0;

    if (c < 64) {
        const float* inq = g_qkv + (size_t)(b*192 + c)*NN;
        const float* ink = g_qkv + (size_t)(b*192 + 64 + c)*NN;
        float wq[9], wk[9];
#pragma unroll
        for (int q = 0; q < 9; q++) { wq[q] = wdw[c*9 + q]; wk[q] = wdw[(64 + c)*9 + q]; }
        float qa[8], ka[8];
#pragma unroll
        for (int u = 0; u < 8; u++) { qa[u] = 0.0f; ka[u] = 0.0f; }
#pragma unroll
        for (int ky = 0; ky < 3; ky++) {
            int ii = i + ky - 1;
            if (ii < 0 || ii > 255) continue;
            {
                const float* rq = inq + ii*256;
                float4 a0 = *(const float4*)(rq + j0);
                float4 a1 = *(const float4*)(rq + j0 + 4);
                float e[10];
                e[0] = (j0 > 0)   ? rq[j0 - 1] : 0.0f;
                e[1]=a0.x; e[2]=a0.y; e[3]=a0.z; e[4]=a0.w;
                e[5]=a1.x; e[6]=a1.y; e[7]=a1.z; e[8]=a1.w;
                e[9] = (j0 < 248) ? rq[j0 + 8] : 0.0f;
                float w0 = wq[ky*3+0], w1 = wq[ky*3+1], w2 = wq[ky*3+2];
#pragma unroll
                for (int u = 0; u < 8; u++) qa[u] += w0*e[u] + w1*e[u+1] + w2*e[u+2];
            }
            {
                const float* rk = ink + ii*256;
                float4 a0 = *(const float4*)(rk + j0);
                float4 a1 = *(const float4*)(rk + j0 + 4);
                float e[10];
                e[0] = (j0 > 0)   ? rk[j0 - 1] : 0.0f;
                e[1]=a0.x; e[2]=a0.y; e[3]=a0.z; e[4]=a0.w;
                e[5]=a1.x; e[6]=a1.y; e[7]=a1.z; e[8]=a1.w;
                e[9] = (j0 < 248) ? rk[j0 + 8] : 0.0f;
                float w0 = wk[ky*3+0], w1 = wk[ky*3+1], w2 = wk[ky*3+2];
#pragma unroll
                for (int u = 0; u < 8; u++) ka[u] += w0*e[u] + w1*e[u+1] + w2*e[u+2];
            }
        }
        float2* dst = ((float2*)g_dw) + (size_t)(b*64 + c)*NN + p;
#pragma unroll
        for (int u = 0; u < 4; u++) {
            float4 s4; s4.x = qa[2*u]; s4.y = ka[2*u]; s4.z = qa[2*u+1]; s4.w = ka[2*u+1];
            *(float4*)(dst + 2*u) = s4;
        }
        float sq = 0.0f, sk = 0.0f;
#pragma unroll
        for (int u = 0; u < 8; u++) { sq += qa[u]*qa[u]; sk += ka[u]*ka[u]; }
#pragma unroll
        for (int s = 16; s > 0; s >>= 1) {
            sq += __shfl_down_sync(0xffffffffu, sq, s);
            sk += __shfl_down_sync(0xffffffffu, sk, s);
        }
        if ((t & 31) == 0) { red[t >> 5][0] = sq; red[t >> 5][1] = sk; }
        __syncthreads();
        if (t == 0) {
            float s1s = 0.0f, s2s = 0.0f;
#pragma unroll
            for (int w2 = 0; w2 < 8; w2++) { s1s += red[w2][0]; s2s += red[w2][1]; }
            atomicAdd(&g_nq[b*64 + c], s1s);
            atomicAdd(&g_nk[b*64 + c], s2s);
        }
    } else {
        int vc = c - 64;
        const float* in = g_qkv + (size_t)(b*192 + 128 + vc)*NN;
        float wl[9];
#pragma unroll
        for (int q = 0; q < 9; q++) wl[q] = wdw[(128 + vc)*9 + q];
        vhist[t] = 0;
        __syncthreads();
        float a[8];
#pragma unroll
        for (int u = 0; u < 8; u++) a[u] = 0.0f;
#pragma unroll
        for (int ky = 0; ky < 3; ky++) {
            int ii = i + ky - 1;
            if (ii < 0 || ii > 255) continue;
            const float* row = in + ii*256;
            float4 a0 = *(const float4*)(row + j0);
            float4 a1 = *(const float4*)(row + j0 + 4);
            float e[10];
            e[0] = (j0 > 0)   ? row[j0 - 1] : 0.0f;
            e[1]=a0.x; e[2]=a0.y; e[3]=a0.z; e[4]=a0.w;
            e[5]=a1.x; e[6]=a1.y; e[7]=a1.z; e[8]=a1.w;
            e[9] = (j0 < 248) ? row[j0 + 8] : 0.0f;
            float w0 = wl[ky*3+0], w1 = wl[ky*3+1], w2 = wl[ky*3+2];
#pragma unroll
            for (int u = 0; u < 8; u++) a[u] += w0*e[u] + w1*e[u+1] + w2*e[u+2];
        }
        int seg = b*64 + vc;
        unsigned kk[8];
#pragma unroll
        for (int u = 0; u < 8; u++) kk[u] = fkey(a[u]);
        unsigned* dst = K0 + (size_t)seg*NN + p;
        uint4 k0; k0.x=kk[0]; k0.y=kk[1]; k0.z=kk[2]; k0.w=kk[3];
        uint4 k1; k1.x=kk[4]; k1.y=kk[5]; k1.z=kk[6]; k1.w=kk[7];
        *(uint4*)dst = k0;
        *(uint4*)(dst + 4) = k1;
#pragma unroll
        for (int u = 0; u < 8; u++)
            atomicAdd(&vhist[(kk[u] >> 8) & 255u], 1u);
        __syncthreads();
        unsigned v = vhist[t];
        if (v) {
            int blk = blockIdx.y >> 1;   // 8 rows/block = 2048 px; 4096-px sort block = y/2
            atomicAdd(&cntA[(seg*16 + blk)*256 + t], v);
        }
    }
}

// K5: per-segment scan of counts -> within-segment offsets
__global__ __launch_bounds__(256) void k_scan(unsigned* __restrict__ cnt) {
    __shared__ unsigned cl[16][256];
    __shared__ unsigned scn[256];
    int seg = blockIdx.x, t = threadIdx.x;
    for (int blk = 0; blk < 16; blk++)
        cl[blk][t] = cnt[(seg*16 + blk)*256 + t];
    __syncthreads();
    unsigned s = 0;
    for (int blk = 0; blk < 16; blk++) s += cl[blk][t];
    unsigned mytot = s;
    scn[t] = s;
    __syncthreads();
    for (int off = 1; off < 256; off <<= 1) {
        unsigned v = scn[t];
        unsigned add = (t >= off) ? scn[t - off] : 0;
        __syncthreads();
        scn[t] = v + add;
        __syncthreads();
    }
    unsigned run = scn[t] - mytot;
    for (int blk = 0; blk < 16; blk++) {
        cnt[(seg*16 + blk)*256 + t] = run;
        run += cl[blk][t];
    }
}

// K6: stable scatter (R9-proven)
__global__ __launch_bounds__(256) void k_scatter(const unsigned* __restrict__ srcK,
                                                 const unsigned short* __restrict__ srcP,
                                                 unsigned* __restrict__ dstK,
                                                 unsigned short* __restrict__ dstP,
                                                 int shift,
                                                 const unsigned* __restrict__ cntCur,
                                                 unsigned* __restrict__ cntNext, int nextshift,
                                                 float* __restrict__ vout,
                                                 unsigned short* __restrict__ iout) {
    extern __shared__ char sm[];
    unsigned* stageK        = (unsigned*)sm;
    unsigned short* stageP  = (unsigned short*)(sm + 16384);
    unsigned* h2            = (unsigned*)(sm + 24576);
    ull* wcnt64             = (ull*)(sm + 40960);
    unsigned* scn           = (unsigned*)(sm + 43008);
    unsigned* offsC         = (unsigned*)(sm + 44032);
    unsigned short* rankOf  = (unsigned short*)(sm + 45056);
    unsigned short* runbase = (unsigned short*)(sm + 53248);
    unsigned short* startLoc= (unsigned short*)(sm + 53760);

    int t = threadIdx.x;
    int w = t >> 5;
    unsigned ltm = lmask_lt();
    int base = blockIdx.x * 4096;
    int seg = base >> 16;
    bool doNext = (cntNext != nullptr);
    bool isFinal = (vout != nullptr);

    runbase[t] = 0;
    offsC[t] = cntCur[blockIdx.x*256 + t];
    if (doNext)
        for (int m = t; m < 4096; m += 256) h2[m] = 0;

    unsigned key[16];
    unsigned short pos[16];
#pragma unroll
    for (int r = 0; r < 16; r++) key[r] = srcK[base + r*256 + t];
    if (srcP) {
#pragma unroll
        for (int r = 0; r < 16; r++) pos[r] = srcP[base + r*256 + t];
    } else {
#pragma unroll
        for (int r = 0; r < 16; r++) pos[r] = (unsigned short)((base + r*256 + t) & 65535);
    }

    ull wmask = (1ull << (8*w)) - 1ull;
    for (int r = 0; r < 16; r++) {
        wcnt64[t] = 0ull;
        __syncthreads();
        unsigned d = (key[r] >> shift) & 255u;
        unsigned mask = __match_any_sync(0xffffffffu, d);
        unsigned lr = __popc(mask & ltm);
        if (lr == 0)
            ((unsigned char*)&wcnt64[d])[w] = (unsigned char)__popc(mask);
        __syncthreads();
        ull cd = wcnt64[d];
        ull ct = wcnt64[t];
        rankOf[r*256 + t] = (unsigned short)((unsigned)runbase[d] + bytesum(cd & wmask) + lr);
        __syncthreads();
        runbase[t] = (unsigned short)((unsigned)runbase[t] + bytesum(ct));
    }
    __syncthreads();
    unsigned mycnt = runbase[t];
    scn[t] = mycnt;
    __syncthreads();
    for (int off = 1; off < 256; off <<= 1) {
        unsigned v = scn[t];
        unsigned add = (t >= off) ? scn[t - off] : 0;
        __syncthreads();
        scn[t] = v + add;
        __syncthreads();
    }
    startLoc[t] = (unsigned short)(scn[t] - mycnt);
    __syncthreads();
#pragma unroll
    for (int r = 0; r < 16; r++) {
        unsigned d = (key[r] >> shift) & 255u;
        unsigned rank = rankOf[r*256 + t];
        unsigned sl = startLoc[d];
        stageK[sl + rank] = key[r];
        stageP[sl + rank] = pos[r];
        if (doNext) {
            unsigned ds = offsC[d] + rank;
            unsigned d2 = (key[r] >> nextshift) & 255u;
            atomicAdd(&h2[(ds >> 12)*256 + d2], 1u);
        }
    }
    __syncthreads();
    unsigned segbase = (unsigned)seg << 16;
    if (!isFinal) {
#pragma unroll
        for (int r = 0; r < 16; r++) {
            int j = r*256 + t;
            unsigned k2 = stageK[j];
            unsigned d = (k2 >> shift) & 255u;
            unsigned dsti = segbase + offsC[d] + (unsigned)j - startLoc[d];
            dstK[dsti] = k2;
            dstP[dsti] = stageP[j];
        }
    } else {
#pragma unroll
        for (int r = 0; r < 16; r++) {
            int j = r*256 + t;
            unsigned k2 = stageK[j];
            unsigned d = (k2 >> shift) & 255u;
            unsigned dsti = segbase + offsC[d] + (unsigned)j - startLoc[d];
            vout[dsti] = fdec(k2);
            iout[dsti] = stageP[j];
        }
    }
    if (doNext) {
        __syncthreads();
        for (int m = t; m < 4096; m += 256) {
            unsigned v = h2[m];
            if (v) atomicAdd(&cntNext[(seg*16 + (m >> 8))*256 + (m & 255)], v);
        }
    }
}

// K7: raw 8x8 Gram per (b,head)
__global__ __launch_bounds__(256) void k_attn(const unsigned short* __restrict__ iall) {
    __shared__ float wsum[8][64];
    int bh = blockIdx.x; int b = bh >> 3, h = bh & 7;
    const float2* qk = ((const float2*)g_dw) + (size_t)(b*64 + h*8)*NN;
    const unsigned short* ip = iall + (size_t)(b*64 + h*8)*NN;
    float acc[64];
#pragma unroll
    for (int m = 0; m < 64; m++) acc[m] = 0.0f;
    int i0 = blockIdx.y * 4096;
    for (int i = i0 + threadIdx.x; i < i0 + 4096; i += 256) {
        unsigned id[8]; float qv[8], kv[8];
#pragma unroll
        for (int c = 0; c < 8; c++) id[c] = __ldcs(ip + c*NN + i);
#pragma unroll
        for (int c = 0; c < 8; c++) {
            float2 p = qk[(size_t)c*NN + id[c]];
            qv[c] = p.x; kv[c] = p.y;
        }
#pragma unroll
        for (int c = 0; c < 8; c++)
#pragma unroll
            for (int d = 0; d < 8; d++) acc[c*8+d] += qv[c]*kv[d];
    }
#pragma unroll
    for (int m = 0; m < 64; m++) {
#pragma unroll
        for (int s = 16; s > 0; s >>= 1)
            acc[m] += __shfl_down_sync(0xffffffffu, acc[m], s);
    }
    int w = threadIdx.x >> 5;
    if ((threadIdx.x & 31) == 0)
#pragma unroll
        for (int m = 0; m < 64; m++) wsum[w][m] = acc[m];
    __syncthreads();
    if (threadIdx.x < 64) {
        float s = 0.0f;
#pragma unroll
        for (int w2 = 0; w2 < 8; w2++) s += wsum[w2][threadIdx.x];
        atomicAdd(&g_attnraw[bh*64 + threadIdx.x], s);
    }
}

// K8: normalize + temperature + softmax
__global__ __launch_bounds__(512) void k_softmax(const float* __restrict__ temp) {
    int t = threadIdx.x;
    int b = t >> 6, h = (t >> 3) & 7, c = t & 7;
    int bh = b*8 + h;
    float nq = fmaxf(sqrtf(g_nq[b*64 + h*8 + c]), 1e-12f);
    float tp = temp[h];
    float a[8];
    float mx = -FLT_MAX;
#pragma unroll
    for (int d = 0; d < 8; d++) {
        float nk = fmaxf(sqrtf(g_nk[b*64 + h*8 + d]), 1e-12f);
        a[d] = g_attnraw[bh*64 + c*8 + d] / (nq*nk) * tp;
        mx = fmaxf(mx, a[d]);
    }
    float s = 0.0f;
#pragma unroll
    for (int d = 0; d < 8; d++) { a[d] = expf(a[d] - mx); s += a[d]; }
    float inv = 1.0f / s;
#pragma unroll
    for (int d = 0; d < 8; d++) g_attn[bh*64 + c*8 + d] = a[d]*inv;
}

// K9: out = attn @ v_s, scattered back; fused per-channel sum/max
__global__ __launch_bounds__(256) void k_av(const float* __restrict__ vall,
                                            const unsigned short* __restrict__ iall) {
    int bh = blockIdx.y; int b = bh >> 3, h = bh & 7;
    __shared__ float a[64];
    __shared__ float redS[8][8];
    __shared__ unsigned redM[8][8];
    if (threadIdx.x < 64) a[threadIdx.x] = g_attn[bh*64 + threadIdx.x];
    __syncthreads();
    int n = blockIdx.x*256 + threadIdx.x;
    int base = (b*64 + h*8)*NN;
    float v[8]; unsigned id[8];
#pragma unroll
    for (int d = 0; d < 8; d++) {
        v[d] = __ldcs(vall + base + d*NN + n);
        id[d] = __ldcs(iall + base + d*NN + n);
    }
    int w = threadIdx.x >> 5, lane = threadIdx.x & 31;
#pragma unroll
    for (int c = 0; c < 8; c++) {
        float s = 0.0f;
#pragma unroll
        for (int d = 0; d < 8; d++) s += a[c*8+d]*v[d];
        g_out[base + c*NN + id[c]] = s;
        float ssum = s;
        unsigned smax = fkey(s);
#pragma unroll
        for (int sh = 16; sh > 0; sh >>= 1) {
            ssum += __shfl_down_sync(0xffffffffu, ssum, sh);
            smax = max(smax, __shfl_down_sync(0xffffffffu, smax, sh));
        }
        if (lane == 0) { redS[c][w] = ssum; redM[c][w] = smax; }
    }
    __syncthreads();
    if (threadIdx.x < 8) {
        int c = threadIdx.x;
        float s = 0.0f; unsigned m = 0;
#pragma unroll
        for (int w2 = 0; w2 < 8; w2++) { s += redS[c][w2]; m = max(m, redM[c][w2]); }
        atomicAdd(&g_chsum[b*64 + h*8 + c], s);
        atomicMax(&g_chmaxu[b*64 + h*8 + c], m);
    }
}

// K10: channel attention
__global__ __launch_bounds__(64) void k_ca(const float* __restrict__ wfc1, const float* __restrict__ wfc2) {
    int b = blockIdx.x, c = threadIdx.x;
    __shared__ float mv[64], xv[64];
    mv[c] = g_chsum[b*64 + c] * (1.0f/65536.0f);
    xv[c] = fdec(g_chmaxu[b*64 + c]);
    __syncthreads();
    float r1[4], r2[4];
#pragma unroll
    for (int j = 0; j < 4; j++) {
        float s1 = 0.0f, s2 = 0.0f;
        for (int cc = 0; cc < 64; cc++) {
            float w = wfc1[j*64 + cc];
            s1 += mv[cc]*w; s2 += xv[cc]*w;
        }
        r1[j] = s1 * sigm(s1);
        r2[j] = s2 * sigm(s2);
    }
    float t1 = 0.0f, t2 = 0.0f;
#pragma unroll
    for (int j = 0; j < 4; j++) { t1 += r1[j]*wfc2[c*4 + j]; t2 += r2[j]*wfc2[c*4 + j]; }
    g_ca[b*64 + c] = sigm(t1) + sigm(t2);
}

// K11: spatial stats — 4 px/thread, float4
__global__ __launch_bounds__(256) void k_sp() {
    int b = blockIdx.y;
    int n0 = (blockIdx.x*256 + threadIdx.x)*4;
    __shared__ float cas[64];
    if (threadIdx.x < 64) cas[threadIdx.x] = g_ca[b*64 + threadIdx.x];
    __syncthreads();
    float4 s = make_float4(0.f,0.f,0.f,0.f);
    float4 mx = make_float4(-FLT_MAX,-FLT_MAX,-FLT_MAX,-FLT_MAX);
    float4 mn = make_float4(FLT_MAX,FLT_MAX,FLT_MAX,FLT_MAX);
    for (int c = 0; c < 64; c++) {
        float4 v = *(const float4*)(g_out + (size_t)(b*64 + c)*NN + n0);
        float cc = cas[c];
        v.x *= cc; v.y *= cc; v.z *= cc; v.w *= cc;
        s.x += v.x; s.y += v.y; s.z += v.z; s.w += v.w;
        mx.x = fmaxf(mx.x, v.x); mx.y = fmaxf(mx.y, v.y); mx.z = fmaxf(mx.z, v.z); mx.w = fmaxf(mx.w, v.w);
        mn.x = fminf(mn.x, v.x); mn.y = fminf(mn.y, v.y); mn.z = fminf(mn.z, v.z); mn.w = fminf(mn.w, v.w);
    }
    float4 mean; mean.x = s.x*(1.0f/64.0f); mean.y = s.y*(1.0f/64.0f);
    mean.z = s.z*(1.0f/64.0f); mean.w = s.w*(1.0f/64.0f);
    *(float4*)(g_sp + (size_t)(b*4 + 0)*NN + n0) = mean;
    *(float4*)(g_sp + (size_t)(b*4 + 1)*NN + n0) = mx;
    *(float4*)(g_sp + (size_t)(b*4 + 2)*NN + n0) = mn;
    *(float4*)(g_sp + (size_t)(b*4 + 3)*NN + n0) = s;
}

// K12: 7x7 conv (4->1) + silu + 1x1 + sigmoid
__global__ __launch_bounds__(256) void k_sa(const float* __restrict__ wsp1, const float* __restrict__ bsp1,
                                            const float* __restrict__ wsp2, const float* __restrict__ bsp2) {
    __shared__ float tile[4][22][22];
    __shared__ float ws[196];
    int b = blockIdx.z;
    int y0 = blockIdx.y*16, x0 = blockIdx.x*16;
    int tx = threadIdx.x & 15, ty = threadIdx.x >> 4;
    int tid = threadIdx.x;
    if (tid < 196) ws[tid] = wsp1[tid];
    for (int m = tid; m < 4*484; m += 256) {
        int ic = m / 484, rr = m % 484;
        int iy = rr / 22, ix = rr % 22;
        int gy = y0 + iy - 3, gx = x0 + ix - 3;
        tile[ic][iy][ix] = (gy >= 0 && gy < 256 && gx >= 0 && gx < 256)
                           ? g_sp[(b*4 + ic)*NN + gy*256 + gx] : 0.0f;
    }
    __syncthreads();
    float acc = 0.0f;
#pragma unroll
    for (int ic = 0; ic < 4; ic++)
#pragma unroll
        for (int ky = 0; ky < 7; ky++)
#pragma unroll
            for (int kx = 0; kx < 7; kx++)
                acc += ws[ic*49 + ky*7 + kx] * tile[ic][ty+ky][tx+kx];
    float s = acc + bsp1[0];
    float sl = s * sigm(s);
    float t2 = wsp2[0]*sl + bsp2[0];
    g_sa[b*NN + (y0+ty)*256 + x0+tx] = sigm(t2);
}

// K13: projection GEMM + ca*sa scaling + inverse permutations (c<32)
__global__ __launch_bounds__(256) void k_proj(const float* __restrict__ wproj, float* __restrict__ out) {
    __shared__ float xs[64][128];
    __shared__ float wp[64][64];
    __shared__ float sas[128];
    __shared__ float cas[64];
    int b = blockIdx.y;
    int p0 = blockIdx.x * 128, t = threadIdx.x;
    if (t < 64) cas[t] = g_ca[b*64 + t];
    if (t < 128) sas[t] = g_sa[b*NN + p0 + t];
    __syncthreads();
    for (int m = t; m < 64*32; m += 256) {
        int c = m >> 5, q = m & 31;
        float4 v = ((const float4*)(g_out + (size_t)(b*64 + c)*NN + p0))[q];
        float cc = cas[c];
        v.x *= cc; v.y *= cc; v.z *= cc; v.w *= cc;
        ((float4*)&xs[c][0])[q] = v;
    }
    for (int m = t; m < 4096; m += 256) {
        int o = m >> 6, c = m & 63;
        wp[o][c] = wproj[o*64 + c];
    }
    __syncthreads();
    int ob = (t >> 5) * 8, pb = (t & 31) * 4;
    float acc[8][4];
#pragma unroll
    for (int u = 0; u < 8; u++)
#pragma unroll
        for (int v = 0; v < 4; v++) acc[u][v] = 0.0f;
#pragma unroll 4
    for (int c0 = 0; c0 < 64; c0 += 4) {
        float4 wv[8];
#pragma unroll
        for (int u = 0; u < 8; u++) wv[u] = *(const float4*)&wp[ob + u][c0];
#pragma unroll
        for (int cc = 0; cc < 4; cc++) {
            float4 xv = *(const float4*)&xs[c0 + cc][pb];
#pragma unroll
            for (int u = 0; u < 8; u++) {
                float wu = (cc == 0) ? wv[u].x : (cc == 1) ? wv[u].y : (cc == 2) ? wv[u].z : wv[u].w;
                acc[u][0] += wu*xv.x; acc[u][1] += wu*xv.y;
                acc[u][2] += wu*xv.z; acc[u][3] += wu*xv.w;
            }
        }
    }
#pragma unroll
    for (int u = 0; u < 8; u++) {
        int o = ob + u;
        if (o >= 32) {
#pragma unroll
            for (int v = 0; v < 4; v++)
                out[(b*64 + o)*NN + p0 + pb + v] = acc[u][v] * sas[pb + v];
        } else {
            int ibase = (b*32 + o) * NN;
#pragma unroll
            for (int v = 0; v < 4; v++) {
                int n = p0 + pb + v;
                int q = n >> 8, p = n & 255;
                int j = (int)g_idxw[ibase + q*256 + p];
                int r = (int)g_idxh[ibase + q*256 + j];
                out[(b*64 + o)*NN + r*256 + j] = acc[u][v] * sas[pb + v];
            }
        }
    }
}

extern "C" void kernel_launch(void* const* d_in, const int* in_sizes, int n_in,
                              void* d_out, int out_size) {
    const float* x     = (const float*)d_in[0];
    const float* temp  = (const float*)d_in[1];
    const float* wqkv  = (const float*)d_in[2];
    const float* wdw   = (const float*)d_in[3];
    const float* wfc1  = (const float*)d_in[4];
    const float* wfc2  = (const float*)d_in[5];
    const float* wsp1  = (const float*)d_in[6];
    const float* bsp1  = (const float*)d_in[7];
    const float* wsp2  = (const float*)d_in[8];
    const float* bsp2  = (const float*)d_in[9];
    const float* wproj = (const float*)d_in[10];
    float* out = (float*)d_out;

    cudaFuncSetAttribute(k_scatter, cudaFuncAttributeMaxDynamicSharedMemorySize, 54272);
    cudaFuncSetAttribute(k_qkv, cudaFuncAttributeMaxDynamicSharedMemorySize, 82944);

    void *pS0, *pS1, *pA, *pB, *pC, *pvx, *pqkv;
    cudaGetSymbolAddress(&pS0, g_keys0);
    cudaGetSymbolAddress(&pS1, g_keys1);
    cudaGetSymbolAddress(&pA, g_cntA);
    cudaGetSymbolAddress(&pB, g_cntB);
    cudaGetSymbolAddress(&pC, g_cntC);
    cudaGetSymbolAddress(&pvx, g_x);
    cudaGetSymbolAddress(&pqkv, g_qkv);
    unsigned* K0 = (unsigned*)pS0;
    unsigned short* P0 = (unsigned short*)((unsigned*)pS0 + TOT);
    unsigned* K1 = (unsigned*)pS1;
    unsigned short* P1 = (unsigned short*)((unsigned*)pS1 + TOT);
    unsigned* cntA = (unsigned*)pA;
    unsigned* cntB = (unsigned*)pB;
    unsigned* cntC = (unsigned*)pC;
    float* vall = (float*)pvx;
    unsigned short* iall = (unsigned short*)pqkv;

    k_colsort<<<8192, 256>>>(x, cntB);
    k_rowsort<<<8192, 256>>>(cntA, cntC);
    k_qkv<<<dim3(NN/256, BB), 256, 82944>>>(wqkv, x);
    k_dwconv<<<dim3(BB*128, 32), 256>>>(wdw, K0, cntA);

    // segmented radix sort: 3 passes on key bits [8,32)
    k_scan<<<512, 256>>>(cntA);
    k_scatter<<<8192, 256, 54272>>>(K0, nullptr, K1, P1, 8, cntA, cntB, 16, nullptr, nullptr);
    k_scan<<<512, 256>>>(cntB);
    k_scatter<<<8192, 256, 54272>>>(K1, P1, K0, P0, 16, cntB, cntC, 24, nullptr, nullptr);
    k_scan<<<512, 256>>>(cntC);
    k_scatter<<<8192, 256, 54272>>>(K0, P0, nullptr, nullptr, 24, cntC, nullptr, 0, vall, iall);

    k_attn<<<dim3(BB*HEADS, 16), 256>>>(iall);
    k_softmax<<<1, 512>>>(temp);
    k_av<<<dim3(NN/256, BB*HEADS), 256>>>(vall, iall);
    k_ca<<<BB, 64>>>(wfc1, wfc2);
    k_sp<<<dim3(NN/1024, BB), 256>>>();
    k_sa<<<dim3(16, 16, BB), 256>>>(wsp1, bsp1, wsp2, bsp2);
    k_proj<<<dim3(NN/128, BB), 256>>>(wproj, out);
}